// round 1
// baseline (speedup 1.0000x reference)
#include <cuda_runtime.h>
#include <cuda_bf16.h>

// Problem constants
#define BB 8
#define CC 128
#define OO 256
#define HH 96
#define WW 96
#define SS (HH*WW)          // 9216
#define KK 9                // 3x3 taps
#define CK (CC*KK)          // 1152

// ---------------- static device scratch (no allocs allowed) ----------------
__device__ __align__(16) float g_xt[(size_t)BB*SS*CC];   // x in NHWC: [(b*S+s)*C + c]
__device__ __align__(16) float g_wt[CK*OO];              // weight^T: [(c*9+k)*O + o]
__device__ float4 g_mw[(size_t)BB*SS*KK];                // 4 corner weights (mask premult)
__device__ int4   g_mi[(size_t)BB*SS*KK];                // 4 clamped corner spatial idx (y*W+x)

// ---------------- f32x2 helpers (sm_103a packed fp32) ----------------
__device__ __forceinline__ void fma2(unsigned long long &d, unsigned long long a,
                                     unsigned long long b) {
    asm("fma.rn.f32x2 %0, %1, %2, %0;" : "+l"(d) : "l"(a), "l"(b));
}
__device__ __forceinline__ unsigned long long dup2(float v) {
    unsigned long long r;
    asm("mov.b64 %0, {%1, %1};" : "=l"(r) : "f"(v));
    return r;
}
__device__ __forceinline__ void unpack2(unsigned long long v, float &lo, float &hi) {
    asm("mov.b64 {%0, %1}, %2;" : "=f"(lo), "=f"(hi) : "l"(v));
}

// ---------------- kernel 0a: NCHW -> NHWC transpose of x ----------------
__global__ void transpose_x_kernel(const float* __restrict__ x) {
    __shared__ float tile[32][33];
    int s0 = blockIdx.x * 32;
    int c0 = blockIdx.y * 32;
    int b  = blockIdx.z;
    int tx = threadIdx.x, ty = threadIdx.y;
    #pragma unroll
    for (int i = 0; i < 4; i++) {
        int c = c0 + ty + i * 8;
        tile[ty + i * 8][tx] = x[((size_t)b * CC + c) * SS + s0 + tx];
    }
    __syncthreads();
    #pragma unroll
    for (int i = 0; i < 4; i++) {
        int s = s0 + ty + i * 8;
        g_xt[((size_t)b * SS + s) * CC + c0 + tx] = tile[tx][ty + i * 8];
    }
}

// ---------------- kernel 0b: weight [O][C*9] -> [C*9][O] ----------------
__global__ void transpose_w_kernel(const float* __restrict__ w) {
    __shared__ float tile[32][33];
    int ck0 = blockIdx.x * 32;
    int o0  = blockIdx.y * 32;
    int tx = threadIdx.x, ty = threadIdx.y;
    #pragma unroll
    for (int i = 0; i < 4; i++) {
        int o = o0 + ty + i * 8;
        tile[ty + i * 8][tx] = w[(size_t)o * CK + ck0 + tx];
    }
    __syncthreads();
    #pragma unroll
    for (int i = 0; i < 4; i++) {
        int ck = ck0 + ty + i * 8;
        g_wt[(size_t)ck * OO + o0 + tx] = tile[tx][ty + i * 8];
    }
}

// ---------------- kernel 1: offset+mask conv, emit sampling meta ----------------
// block (16,16) covers a 16x16 output tile of one batch image.
__global__ __launch_bounds__(256) void offmask_kernel(
    const float* __restrict__ x,
    const float* __restrict__ ow, const float* __restrict__ ob,
    const float* __restrict__ mw, const float* __restrict__ mb)
{
    __shared__ float xs[8][18][18];   // 8 channels x (16+2)^2 halo tile
    __shared__ float ws[27][8][9];    // 27 out-ch x 8 in-ch x 9 taps

    int tx = threadIdx.x, ty = threadIdx.y;
    int tid = ty * 16 + tx;
    int b = blockIdx.z;
    int hb = blockIdx.y * 16, wb = blockIdx.x * 16;
    int ho = hb + ty, wo = wb + tx;

    float acc[27];
    #pragma unroll
    for (int oc = 0; oc < 18; oc++) acc[oc] = ob[oc];
    #pragma unroll
    for (int oc = 0; oc < 9; oc++) acc[18 + oc] = mb[oc];

    for (int c0 = 0; c0 < CC; c0 += 8) {
        __syncthreads();
        // load 8-channel halo tile (zero padded)
        for (int idx = tid; idx < 8 * 18 * 18; idx += 256) {
            int c = idx / 324;
            int rem = idx - c * 324;
            int r = rem / 18, col = rem - r * 18;
            int gy = hb + r - 1, gx = wb + col - 1;
            float v = 0.f;
            if ((unsigned)gy < (unsigned)HH && (unsigned)gx < (unsigned)WW)
                v = x[(((size_t)b * CC + c0 + c) * HH + gy) * WW + gx];
            xs[c][r][col] = v;
        }
        // load combined weights chunk
        for (int idx = tid; idx < 27 * 8 * 9; idx += 256) {
            int oc = idx / 72;
            int rem = idx - oc * 72;
            int c = rem / 9, t = rem - c * 9;
            float v = (oc < 18)
                ? ow[((size_t)oc * CC + (c0 + c)) * 9 + t]
                : mw[((size_t)(oc - 18) * CC + (c0 + c)) * 9 + t];
            ws[oc][c][t] = v;
        }
        __syncthreads();

        #pragma unroll
        for (int c = 0; c < 8; c++) {
            float xv[9];
            #pragma unroll
            for (int t = 0; t < 9; t++) xv[t] = xs[c][ty + t / 3][tx + t % 3];
            #pragma unroll
            for (int oc = 0; oc < 27; oc++) {
                #pragma unroll
                for (int t = 0; t < 9; t++) acc[oc] += xv[t] * ws[oc][c][t];
            }
        }
    }

    // epilogue: per tap, compute bilinear corner weights/indices
    size_t sid = ((size_t)b * SS + (size_t)ho * WW + wo) * KK;
    #pragma unroll
    for (int k = 0; k < 9; k++) {
        int kh = k / 3, kw = k % 3;
        float py = (float)(ho + kh - 1) + acc[2 * k];
        float px = (float)(wo + kw - 1) + acc[2 * k + 1];
        float m = 1.f / (1.f + __expf(-acc[18 + k]));

        float y0f = floorf(py), x0f = floorf(px);
        float wy1 = py - y0f, wx1 = px - x0f;
        float wy0 = 1.f - wy1, wx0 = 1.f - wx1;
        int y0 = (int)y0f, x0i = (int)x0f;
        int y1 = y0 + 1, x1 = x0i + 1;
        bool vy0 = (unsigned)y0  < (unsigned)HH;
        bool vy1 = (unsigned)y1  < (unsigned)HH;
        bool vx0 = (unsigned)x0i < (unsigned)WW;
        bool vx1 = (unsigned)x1  < (unsigned)WW;
        int cy0 = min(max(y0, 0), HH - 1), cy1 = min(max(y1, 0), HH - 1);
        int cx0 = min(max(x0i, 0), WW - 1), cx1 = min(max(x1, 0), WW - 1);

        float w00 = (vy0 && vx0) ? wy0 * wx0 * m : 0.f;
        float w01 = (vy0 && vx1) ? wy0 * wx1 * m : 0.f;
        float w10 = (vy1 && vx0) ? wy1 * wx0 * m : 0.f;
        float w11 = (vy1 && vx1) ? wy1 * wx1 * m : 0.f;

        g_mw[sid + k] = make_float4(w00, w01, w10, w11);
        g_mi[sid + k] = make_int4(cy0 * WW + cx0, cy0 * WW + cx1,
                                  cy1 * WW + cx0, cy1 * WW + cx1);
    }
}

// ---------------- kernel 2: deformable gather + GEMM ----------------
// block: 48 pixels (one row segment) x all 256 output channels, 256 threads.
// thread tile: 6 px x 8 oc, accumulated as f32x2 oc-pairs.
#define TPX   48
#define CCH   32          // channels per sampling chunk
#define SRW   50          // padded s-tile row stride (floats)
#define SROWS (CCH*KK)    // 288 s rows per chunk
#define WR    36          // weight sub-tile rows
#define NSUB  (SROWS/WR)  // 8
#define NSAMP (TPX*KK)    // 432

#define SM_S     0
#define SM_W     (SROWS*SRW)             // 14400
#define SM_MW    (SM_W + WR*OO)          // +9216 = 23616
#define SM_MI    (SM_MW + NSAMP*4)       // +1728 = 25344
#define SM_TOTAL ((SM_MI + NSAMP*4) * 4) // 27072 floats = 108288 bytes

__global__ __launch_bounds__(256, 2) void deform_kernel(
    float* __restrict__ out, const float* __restrict__ bias)
{
    extern __shared__ float sm[];
    float* s_s  = sm + SM_S;
    float* s_w  = sm + SM_W;
    float* s_mw = sm + SM_MW;
    int*   s_mi = (int*)(sm + SM_MI);

    int tid = threadIdx.x;
    int b = blockIdx.z, ho = blockIdx.y, wo0 = blockIdx.x * TPX;

    // copy sampling meta (contiguous 432 float4 / int4)
    size_t sid0 = ((size_t)b * SS + (size_t)ho * WW + wo0) * KK;
    const float4* gmw = g_mw + sid0;
    const int4*   gmi = g_mi + sid0;
    for (int i = tid; i < NSAMP; i += 256) {
        ((float4*)s_mw)[i] = gmw[i];
        ((int4*)s_mi)[i]   = gmi[i];
    }

    unsigned long long acc[6][4];
    #pragma unroll
    for (int i = 0; i < 6; i++)
        #pragma unroll
        for (int j = 0; j < 4; j++) acc[i][j] = 0ull;

    const float* xb = g_xt + (size_t)b * SS * CC;
    int og = tid >> 3;        // 0..31 : oc group (8 oc each)
    int pr = tid & 7;         // 0..7  : px group (6 px each)
    int pb = pr * 6;

    for (int c0 = 0; c0 < CC; c0 += CCH) {
        __syncthreads();      // previous GEMM done reading s_s / meta ready
        // ---- sampling: build s[(cl*9+k)][p] for channels c0..c0+31 ----
        {
            int j = tid & 7;                 // float4 index within 32-ch chunk
            const float* basep = xb + c0 + j * 4;
            for (int ss = tid >> 3; ss < NSAMP; ss += 32) {
                int p = ss / 9, k = ss - p * 9;
                float w0 = s_mw[ss * 4 + 0], w1 = s_mw[ss * 4 + 1];
                float w2 = s_mw[ss * 4 + 2], w3 = s_mw[ss * 4 + 3];
                int i0 = s_mi[ss * 4 + 0], i1 = s_mi[ss * 4 + 1];
                int i2 = s_mi[ss * 4 + 2], i3 = s_mi[ss * 4 + 3];
                float4 v0 = *(const float4*)(basep + i0 * CC);
                float4 v1 = *(const float4*)(basep + i1 * CC);
                float4 v2 = *(const float4*)(basep + i2 * CC);
                float4 v3 = *(const float4*)(basep + i3 * CC);
                float4 sv;
                sv.x = w0 * v0.x + w1 * v1.x + w2 * v2.x + w3 * v3.x;
                sv.y = w0 * v0.y + w1 * v1.y + w2 * v2.y + w3 * v3.y;
                sv.z = w0 * v0.z + w1 * v1.z + w2 * v2.z + w3 * v3.z;
                sv.w = w0 * v0.w + w1 * v1.w + w2 * v2.w + w3 * v3.w;
                int rb = (j * 4) * KK + k;
                s_s[(rb          ) * SRW + p] = sv.x;
                s_s[(rb +     KK ) * SRW + p] = sv.y;
                s_s[(rb + 2 * KK ) * SRW + p] = sv.z;
                s_s[(rb + 3 * KK ) * SRW + p] = sv.w;
            }
        }
        // ---- GEMM over this chunk's 288 ck rows, in 8 sub-tiles of 36 ----
        for (int sub = 0; sub < NSUB; sub++) {
            __syncthreads();
            const float4* gw = (const float4*)(g_wt + (size_t)(c0 * KK + sub * WR) * OO);
            for (int i = tid; i < WR * (OO / 4); i += 256) ((float4*)s_w)[i] = gw[i];
            __syncthreads();

            const float* sbase = s_s + (sub * WR) * SRW + pb;
            const float* wbase = s_w + og * 8;
            #pragma unroll 4
            for (int r = 0; r < WR; r++) {
                float2 sa = *(const float2*)(sbase + r * SRW);
                float2 sb = *(const float2*)(sbase + r * SRW + 2);
                float2 sc = *(const float2*)(sbase + r * SRW + 4);
                ulonglong2 wa = *(const ulonglong2*)(wbase + r * OO);
                ulonglong2 wb2 = *(const ulonglong2*)(wbase + r * OO + 4);
                unsigned long long d[6];
                d[0] = dup2(sa.x); d[1] = dup2(sa.y);
                d[2] = dup2(sb.x); d[3] = dup2(sb.y);
                d[4] = dup2(sc.x); d[5] = dup2(sc.y);
                unsigned long long wv[4] = {wa.x, wa.y, wb2.x, wb2.y};
                #pragma unroll
                for (int ii = 0; ii < 6; ii++)
                    #pragma unroll
                    for (int jj = 0; jj < 4; jj++)
                        fma2(acc[ii][jj], d[ii], wv[jj]);
            }
        }
    }

    // ---- epilogue: write out [B,O,H,W] ----
    float bsv[8];
    #pragma unroll
    for (int q = 0; q < 8; q++) bsv[q] = bias[og * 8 + q];
    size_t obase = ((size_t)b * OO + og * 8) * SS + (size_t)ho * WW + wo0 + pb;
    #pragma unroll
    for (int i = 0; i < 6; i++) {
        #pragma unroll
        for (int jp = 0; jp < 4; jp++) {
            float lo, hi;
            unpack2(acc[i][jp], lo, hi);
            out[obase + (size_t)(jp * 2)     * SS + i] = lo + bsv[jp * 2];
            out[obase + (size_t)(jp * 2 + 1) * SS + i] = hi + bsv[jp * 2 + 1];
        }
    }
}

// ---------------- launch ----------------
extern "C" void kernel_launch(void* const* d_in, const int* in_sizes, int n_in,
                              void* d_out, int out_size) {
    const float* x    = (const float*)d_in[0];
    const float* ow   = (const float*)d_in[1];
    const float* ob   = (const float*)d_in[2];
    const float* mw   = (const float*)d_in[3];
    const float* mb   = (const float*)d_in[4];
    const float* w    = (const float*)d_in[5];
    const float* bias = (const float*)d_in[6];
    float* out = (float*)d_out;

    transpose_x_kernel<<<dim3(SS / 32, CC / 32, BB), dim3(32, 8)>>>(x);
    transpose_w_kernel<<<dim3(CK / 32, OO / 32), dim3(32, 8)>>>(w);
    offmask_kernel<<<dim3(WW / 16, HH / 16, BB), dim3(16, 16)>>>(x, ow, ob, mw, mb);

    cudaFuncSetAttribute(deform_kernel,
                         cudaFuncAttributeMaxDynamicSharedMemorySize, SM_TOTAL);
    deform_kernel<<<dim3(WW / TPX, HH, BB), 256, SM_TOTAL>>>(out, bias);
}

// round 3
// speedup vs baseline: 1.7160x; 1.7160x over previous
#include <cuda_runtime.h>
#include <cuda_bf16.h>
#include <cstdint>

// Problem constants
#define BB 8
#define CC 128
#define OO 256
#define HH 96
#define WW 96
#define SS (HH*WW)          // 9216
#define KK 9                // 3x3 taps
#define CK (CC*KK)          // 1152
#define BSS (BB*SS)         // 73728
#define NCH 18              // K chunks of 64 channels (chunk = tap*2 + half)

// ---------------- static device scratch (no allocs allowed) ----------------
__device__ __align__(16) float g_xt[(size_t)BSS*CC];             // x NHWC
__device__ __align__(16) float4 g_mw[(size_t)KK*BSS];            // corner weights (tap-major)
__device__ __align__(16) int4   g_mi[(size_t)KK*BSS];            // corner indices (tap-major)
__device__ __align__(16) __nv_bfloat16 g_wbh[(size_t)NCH*OO*64]; // weight hi, swizzled tiles
__device__ __align__(16) __nv_bfloat16 g_wbl[(size_t)NCH*OO*64]; // weight lo, swizzled tiles

// ---------------- helpers ----------------
__device__ __forceinline__ uint32_t smem_u32(const void* p) {
    uint32_t a;
    asm("{ .reg .u64 t; cvta.to.shared.u64 t, %1; cvt.u32.u64 %0, t; }" : "=r"(a) : "l"(p));
    return a;
}
// pack two fp32 -> bf16x2 (lo in low half)
__device__ __forceinline__ uint32_t pk2(float lo, float hi) {
    uint32_t r;
    asm("cvt.rn.bf16x2.f32 %0, %1, %2;" : "=r"(r) : "f"(hi), "f"(lo));
    return r;
}
__device__ __forceinline__ void ldsm4(uint32_t* r, uint32_t addr) {
    asm volatile("ldmatrix.sync.aligned.m8n8.x4.shared.b16 {%0,%1,%2,%3}, [%4];"
                 : "=r"(r[0]), "=r"(r[1]), "=r"(r[2]), "=r"(r[3]) : "r"(addr));
}
__device__ __forceinline__ void mma16816(float* c, const uint32_t* a, uint32_t b0, uint32_t b1) {
    asm volatile(
        "mma.sync.aligned.m16n8k16.row.col.f32.bf16.bf16.f32 "
        "{%0,%1,%2,%3}, {%4,%5,%6,%7}, {%8,%9}, {%0,%1,%2,%3};"
        : "+f"(c[0]), "+f"(c[1]), "+f"(c[2]), "+f"(c[3])
        : "r"(a[0]), "r"(a[1]), "r"(a[2]), "r"(a[3]), "r"(b0), "r"(b1));
}
__device__ __forceinline__ void cp16(uint32_t dst, const void* src) {
    asm volatile("cp.async.cg.shared.global [%0], [%1], 16;" :: "r"(dst), "l"(src));
}

// ---------------- kernel 0a: NCHW -> NHWC transpose of x ----------------
__global__ void transpose_x_kernel(const float* __restrict__ x) {
    __shared__ float tile[32][33];
    int s0 = blockIdx.x * 32;
    int c0 = blockIdx.y * 32;
    int b  = blockIdx.z;
    int tx = threadIdx.x, ty = threadIdx.y;
    #pragma unroll
    for (int i = 0; i < 4; i++) {
        int c = c0 + ty + i * 8;
        tile[ty + i * 8][tx] = x[((size_t)b * CC + c) * SS + s0 + tx];
    }
    __syncthreads();
    #pragma unroll
    for (int i = 0; i < 4; i++) {
        int s = s0 + ty + i * 8;
        g_xt[((size_t)b * SS + s) * CC + c0 + tx] = tile[tx][ty + i * 8];
    }
}

// ---------------- kernel 0b: weight -> bf16 hi/lo swizzled chunk tiles ----------------
// chunk ch: tap k = ch>>1, channels c0 = (ch&1)*64. Tile [256 oc rows][64 bf16], SW128.
__global__ void wprep_kernel(const float* __restrict__ w) {
    int o  = blockIdx.x;        // 0..255
    int ch = blockIdx.y;        // 0..17
    int j  = threadIdx.x;       // 0..63
    int k  = ch >> 1, c0 = (ch & 1) * 64;
    float v = w[(size_t)o * CK + (size_t)(c0 + j) * KK + k];
    __nv_bfloat16 hi = __float2bfloat16_rn(v);
    float rv = v - __bfloat162float(hi);
    __nv_bfloat16 lo = __float2bfloat16_rn(rv);
    int byte = o * 128 + j * 2;
    int sw = byte ^ ((byte >> 3) & 0x70);
    *(__nv_bfloat16*)((char*)g_wbh + (size_t)ch * 32768 + sw) = hi;
    *(__nv_bfloat16*)((char*)g_wbl + (size_t)ch * 32768 + sw) = lo;
}

// ---------------- kernel 1: offset+mask conv, emit sampling meta (tap-major) ----------------
__global__ __launch_bounds__(256) void offmask_kernel(
    const float* __restrict__ x,
    const float* __restrict__ ow, const float* __restrict__ ob,
    const float* __restrict__ mw, const float* __restrict__ mb)
{
    __shared__ float xs[8][18][18];
    __shared__ float ws[27][8][9];

    int tx = threadIdx.x, ty = threadIdx.y;
    int tid = ty * 16 + tx;
    int b = blockIdx.z;
    int hb = blockIdx.y * 16, wb = blockIdx.x * 16;
    int ho = hb + ty, wo = wb + tx;

    float acc[27];
    #pragma unroll
    for (int oc = 0; oc < 18; oc++) acc[oc] = ob[oc];
    #pragma unroll
    for (int oc = 0; oc < 9; oc++) acc[18 + oc] = mb[oc];

    for (int c0 = 0; c0 < CC; c0 += 8) {
        __syncthreads();
        for (int idx = tid; idx < 8 * 18 * 18; idx += 256) {
            int c = idx / 324;
            int rem = idx - c * 324;
            int r = rem / 18, col = rem - r * 18;
            int gy = hb + r - 1, gx = wb + col - 1;
            float v = 0.f;
            if ((unsigned)gy < (unsigned)HH && (unsigned)gx < (unsigned)WW)
                v = x[(((size_t)b * CC + c0 + c) * HH + gy) * WW + gx];
            xs[c][r][col] = v;
        }
        for (int idx = tid; idx < 27 * 8 * 9; idx += 256) {
            int oc = idx / 72;
            int rem = idx - oc * 72;
            int c = rem / 9, t = rem - c * 9;
            float v = (oc < 18)
                ? ow[((size_t)oc * CC + (c0 + c)) * 9 + t]
                : mw[((size_t)(oc - 18) * CC + (c0 + c)) * 9 + t];
            ws[oc][c][t] = v;
        }
        __syncthreads();

        #pragma unroll
        for (int c = 0; c < 8; c++) {
            float xv[9];
            #pragma unroll
            for (int t = 0; t < 9; t++) xv[t] = xs[c][ty + t / 3][tx + t % 3];
            #pragma unroll
            for (int oc = 0; oc < 27; oc++) {
                #pragma unroll
                for (int t = 0; t < 9; t++) acc[oc] += xv[t] * ws[oc][c][t];
            }
        }
    }

    size_t pix = (size_t)b * SS + (size_t)ho * WW + wo;
    #pragma unroll
    for (int k = 0; k < 9; k++) {
        int kh = k / 3, kw = k % 3;
        float py = (float)(ho + kh - 1) + acc[2 * k];
        float px = (float)(wo + kw - 1) + acc[2 * k + 1];
        float m = 1.f / (1.f + __expf(-acc[18 + k]));

        float y0f = floorf(py), x0f = floorf(px);
        float wy1 = py - y0f, wx1 = px - x0f;
        float wy0 = 1.f - wy1, wx0 = 1.f - wx1;
        int y0 = (int)y0f, x0i = (int)x0f;
        int y1 = y0 + 1, x1 = x0i + 1;
        bool vy0 = (unsigned)y0  < (unsigned)HH;
        bool vy1 = (unsigned)y1  < (unsigned)HH;
        bool vx0 = (unsigned)x0i < (unsigned)WW;
        bool vx1 = (unsigned)x1  < (unsigned)WW;
        int cy0 = min(max(y0, 0), HH - 1), cy1 = min(max(y1, 0), HH - 1);
        int cx0 = min(max(x0i, 0), WW - 1), cx1 = min(max(x1, 0), WW - 1);

        float w00 = (vy0 && vx0) ? wy0 * wx0 * m : 0.f;
        float w01 = (vy0 && vx1) ? wy0 * wx1 * m : 0.f;
        float w10 = (vy1 && vx0) ? wy1 * wx0 * m : 0.f;
        float w11 = (vy1 && vx1) ? wy1 * wx1 * m : 0.f;

        g_mw[(size_t)k * BSS + pix] = make_float4(w00, w01, w10, w11);
        g_mi[(size_t)k * BSS + pix] = make_int4(cy0 * WW + cx0, cy0 * WW + cx1,
                                                cy1 * WW + cx0, cy1 * WW + cx1);
    }
}

// ---------------- kernel 2: deformable gather + mma.sync bf16-split GEMM ----------------
// CTA: 128 px x 256 oc, 8 warps (2M x 4N), warp tile 64x64, fp32 reg accum.
#define SM_MW4   0          // float4[128]
#define SM_MI4   2048       // int4[128]
#define SM_A     4096       // Ah(16384) + Al(16384)
#define SM_B     36864      // 2 bufs x (Bh 32768 + Bl 32768)
#define SM_TOTAL 167936

__global__ __launch_bounds__(256) void deform_mma_kernel(
    float* __restrict__ out, const float* __restrict__ bias)
{
    extern __shared__ char smem[];
    uint32_t sb = smem_u32(smem);
    int tid = threadIdx.x;
    int wid = tid >> 5;
    int lane = tid & 31;

    int tile = blockIdx.x;
    int b = tile / (SS / 128);
    int s0 = (tile - b * (SS / 128)) * 128;

    float4* s_mw4 = (float4*)(smem + SM_MW4);
    int4*   s_mi4 = (int4*)(smem + SM_MI4);

    // warp geometry
    int wm = wid & 1;                 // M half (64 px)
    int wn = wid >> 1;                // N quarter (64 oc)
    uint32_t rsel = lane & 15;
    uint32_t csel = (uint32_t)(lane >> 4) * 16u;
    uint32_t xorv = (uint32_t)(lane & 7) * 16u;
    uint32_t aLaneOff = (uint32_t)(wm * 64 + rsel) * 128u;
    uint32_t bLaneOff = (uint32_t)(wn * 64 + rsel) * 128u;

    float acc[128];
    #pragma unroll
    for (int i = 0; i < 128; i++) acc[i] = 0.f;

    int g = tid >> 3, j = tid & 7;    // gather lane groups
    const float* xb = g_xt + (size_t)b * SS * CC;

    // prefetch B chunk 0
    {
        const char* gh = (const char*)g_wbh;
        const char* gl = (const char*)g_wbl;
        uint32_t bh = sb + SM_B;
        #pragma unroll
        for (int i = 0; i < 8; i++) {
            uint32_t off = (uint32_t)(tid + i * 256) * 16u;
            cp16(bh + off, gh + off);
            cp16(bh + 32768u + off, gl + off);
        }
        asm volatile("cp.async.commit_group;" ::: "memory");
    }

    for (int ch = 0; ch < NCH; ch++) {
        int buf = ch & 1;
        int c0 = (ch & 1) * 64;

        if ((ch & 1) == 0) {
            if (tid < 128) {
                size_t mo = (size_t)(ch >> 1) * BSS + (size_t)b * SS + s0 + tid;
                s_mw4[tid] = g_mw[mo];
                s_mi4[tid] = g_mi[mo];
            }
            __syncthreads();
        }

        // ---- gather A chunk: 128 px x 64 ch -> bf16 hi/lo swizzled ----
        {
            char* ahp = smem + SM_A;
            char* alp = ahp + 16384;
            const float* xc = xb + c0 + j * 4;
            #pragma unroll
            for (int it = 0; it < 4; it++) {
                int p = g + it * 32;
                float4 wv = s_mw4[p];
                int4  iv = s_mi4[p];
                const float* r0p = xc + (size_t)iv.x * CC;
                const float* r1p = xc + (size_t)iv.y * CC;
                const float* r2p = xc + (size_t)iv.z * CC;
                const float* r3p = xc + (size_t)iv.w * CC;
                #pragma unroll
                for (int h = 0; h < 2; h++) {
                    float4 v0 = *(const float4*)(r0p + h * 32);
                    float4 v1 = *(const float4*)(r1p + h * 32);
                    float4 v2 = *(const float4*)(r2p + h * 32);
                    float4 v3 = *(const float4*)(r3p + h * 32);
                    float sv0 = wv.x * v0.x + wv.y * v1.x + wv.z * v2.x + wv.w * v3.x;
                    float sv1 = wv.x * v0.y + wv.y * v1.y + wv.z * v2.y + wv.w * v3.y;
                    float sv2 = wv.x * v0.z + wv.y * v1.z + wv.z * v2.z + wv.w * v3.z;
                    float sv3 = wv.x * v0.w + wv.y * v1.w + wv.z * v2.w + wv.w * v3.w;
                    uint32_t hiA = pk2(sv0, sv1);
                    uint32_t hiB = pk2(sv2, sv3);
                    float hf0 = __uint_as_float(hiA << 16);
                    float hf1 = __uint_as_float(hiA & 0xFFFF0000u);
                    float hf2 = __uint_as_float(hiB << 16);
                    float hf3 = __uint_as_float(hiB & 0xFFFF0000u);
                    uint32_t loA = pk2(sv0 - hf0, sv1 - hf1);
                    uint32_t loB = pk2(sv2 - hf2, sv3 - hf3);
                    int byte = p * 128 + h * 64 + j * 8;
                    int sw = byte ^ ((byte >> 3) & 0x70);
                    *(uint2*)(ahp + sw) = make_uint2(hiA, hiB);
                    *(uint2*)(alp + sw) = make_uint2(loA, loB);
                }
            }
        }

        // prefetch next B chunk
        if (ch + 1 < NCH) {
            const char* gh = (const char*)g_wbh + (size_t)(ch + 1) * 32768;
            const char* gl = (const char*)g_wbl + (size_t)(ch + 1) * 32768;
            uint32_t bh = sb + SM_B + (uint32_t)((ch + 1) & 1) * 65536u;
            #pragma unroll
            for (int i = 0; i < 8; i++) {
                uint32_t off = (uint32_t)(tid + i * 256) * 16u;
                cp16(bh + off, gh + off);
                cp16(bh + 32768u + off, gl + off);
            }
            asm volatile("cp.async.commit_group;" ::: "memory");
            asm volatile("cp.async.wait_group 1;" ::: "memory");
        } else {
            asm volatile("cp.async.wait_group 0;" ::: "memory");
        }
        __syncthreads();

        // ---- mma: 3 products x 4 ksteps x (4m x 8n) ----
        uint32_t aT0 = sb + SM_A;
        uint32_t bT0 = sb + SM_B + (uint32_t)buf * 65536u;
        #pragma unroll
        for (int prod = 0; prod < 3; prod++) {
            uint32_t aT = aT0 + ((prod == 2) ? 16384u : 0u);
            uint32_t bT = bT0 + ((prod == 1) ? 32768u : 0u);
            #pragma unroll
            for (int s = 0; s < 4; s++) {
                uint32_t colsw = ((uint32_t)(s * 32) + csel) ^ xorv;
                uint32_t aF[4][4], bF[4][4];
                #pragma unroll
                for (int mt = 0; mt < 4; mt++)
                    ldsm4(aF[mt], aT + aLaneOff + (uint32_t)mt * 2048u + colsw);
                #pragma unroll
                for (int ng = 0; ng < 4; ng++)
                    ldsm4(bF[ng], bT + bLaneOff + (uint32_t)ng * 2048u + colsw);
                #pragma unroll
                for (int mt = 0; mt < 4; mt++) {
                    #pragma unroll
                    for (int ng = 0; ng < 4; ng++) {
                        mma16816(&acc[(mt * 8 + ng * 2) * 4],     aF[mt], bF[ng][0], bF[ng][2]);
                        mma16816(&acc[(mt * 8 + ng * 2 + 1) * 4], aF[mt], bF[ng][1], bF[ng][3]);
                    }
                }
            }
        }
        __syncthreads();
    }

    // ---- epilogue: stage each oc-quarter in smem, coalesced store ----
    float* sEp = (float*)(smem + SM_B);
    int r0 = lane >> 2, c0l = (lane & 3) * 2;
    for (int q = 0; q < 4; q++) {
        if (wn == q) {
            #pragma unroll
            for (int mt = 0; mt < 4; mt++) {
                int px = wm * 64 + mt * 16 + r0;
                #pragma unroll
                for (int nn = 0; nn < 8; nn++) {
                    float* a4 = &acc[(mt * 8 + nn) * 4];
                    int ocl = nn * 8 + c0l;
                    sEp[ocl * 132 + px]           = a4[0];
                    sEp[(ocl + 1) * 132 + px]     = a4[1];
                    sEp[ocl * 132 + px + 8]       = a4[2];
                    sEp[(ocl + 1) * 132 + px + 8] = a4[3];
                }
            }
        }
        __syncthreads();
        for (int i = tid; i < 2048; i += 256) {
            int r = i >> 5, c = i & 31;
            float4 v = *(float4*)(sEp + r * 132 + c * 4);
            float bv = __ldg(bias + q * 64 + r);
            v.x += bv; v.y += bv; v.z += bv; v.w += bv;
            *(float4*)(out + ((size_t)b * OO + q * 64 + r) * SS + s0 + c * 4) = v;
        }
        __syncthreads();
    }
}

// ---------------- launch ----------------
extern "C" void kernel_launch(void* const* d_in, const int* in_sizes, int n_in,
                              void* d_out, int out_size) {
    const float* x    = (const float*)d_in[0];
    const float* ow   = (const float*)d_in[1];
    const float* ob   = (const float*)d_in[2];
    const float* mw   = (const float*)d_in[3];
    const float* mb   = (const float*)d_in[4];
    const float* w    = (const float*)d_in[5];
    const float* bias = (const float*)d_in[6];
    float* out = (float*)d_out;

    transpose_x_kernel<<<dim3(SS / 32, CC / 32, BB), dim3(32, 8)>>>(x);
    wprep_kernel<<<dim3(OO, NCH), 64>>>(w);
    offmask_kernel<<<dim3(WW / 16, HH / 16, BB), dim3(16, 16)>>>(x, ow, ob, mw, mb);

    cudaFuncSetAttribute(deform_mma_kernel,
                         cudaFuncAttributeMaxDynamicSharedMemorySize, SM_TOTAL);
    deform_mma_kernel<<<BSS / 128, 256, SM_TOTAL>>>(out, bias);
}

// round 4
// speedup vs baseline: 1.7907x; 1.0435x over previous
#include <cuda_runtime.h>
#include <cuda_bf16.h>
#include <cstdint>

// Problem constants
#define BB 8
#define CC 128
#define OO 256
#define HH 96
#define WW 96
#define SS (HH*WW)          // 9216
#define KK 9                // 3x3 taps
#define CK (CC*KK)          // 1152
#define BSS (BB*SS)         // 73728
#define NCH 18              // K chunks of 64 channels (chunk = tap*2 + half)

// ---------------- static device scratch (no allocs allowed) ----------------
__device__ __align__(16) float g_xt[(size_t)BSS*CC];             // x NHWC
__device__ __align__(16) float4 g_mw[(size_t)KK*BSS];            // corner weights (tap-major)
__device__ __align__(16) int4   g_mi[(size_t)KK*BSS];            // corner indices (tap-major)
__device__ __align__(16) __nv_bfloat16 g_wbh[(size_t)NCH*OO*64]; // weight hi, swizzled tiles
__device__ __align__(16) __nv_bfloat16 g_wbl[(size_t)NCH*OO*64]; // weight lo, swizzled tiles

// ---------------- helpers ----------------
__device__ __forceinline__ uint32_t smem_u32(const void* p) {
    uint32_t a;
    asm("{ .reg .u64 t; cvta.to.shared.u64 t, %1; cvt.u32.u64 %0, t; }" : "=r"(a) : "l"(p));
    return a;
}
// pack two fp32 -> bf16x2 (lo in low half)
__device__ __forceinline__ uint32_t pk2(float lo, float hi) {
    uint32_t r;
    asm("cvt.rn.bf16x2.f32 %0, %1, %2;" : "=r"(r) : "f"(hi), "f"(lo));
    return r;
}
__device__ __forceinline__ void ldsm4(uint32_t* r, uint32_t addr) {
    asm volatile("ldmatrix.sync.aligned.m8n8.x4.shared.b16 {%0,%1,%2,%3}, [%4];"
                 : "=r"(r[0]), "=r"(r[1]), "=r"(r[2]), "=r"(r[3]) : "r"(addr));
}
__device__ __forceinline__ void mma16816(float* c, const uint32_t* a, uint32_t b0, uint32_t b1) {
    asm volatile(
        "mma.sync.aligned.m16n8k16.row.col.f32.bf16.bf16.f32 "
        "{%0,%1,%2,%3}, {%4,%5,%6,%7}, {%8,%9}, {%0,%1,%2,%3};"
        : "+f"(c[0]), "+f"(c[1]), "+f"(c[2]), "+f"(c[3])
        : "r"(a[0]), "r"(a[1]), "r"(a[2]), "r"(a[3]), "r"(b0), "r"(b1));
}
__device__ __forceinline__ void cp16(uint32_t dst, const void* src) {
    asm volatile("cp.async.cg.shared.global [%0], [%1], 16;" :: "r"(dst), "l"(src));
}
// f32x2 packed ops (validated family-safe in round 1)
__device__ __forceinline__ void fma2(unsigned long long &d, unsigned long long a,
                                     unsigned long long b) {
    asm("fma.rn.f32x2 %0, %1, %2, %0;" : "+l"(d) : "l"(a), "l"(b));
}
__device__ __forceinline__ unsigned long long dup2(float v) {
    unsigned long long r;
    asm("mov.b64 %0, {%1, %1};" : "=l"(r) : "f"(v));
    return r;
}
__device__ __forceinline__ unsigned long long pkf2(float lo, float hi) {
    unsigned long long r;
    asm("mov.b64 %0, {%1, %2};" : "=l"(r) : "f"(lo), "f"(hi));
    return r;
}
__device__ __forceinline__ void unpack2(unsigned long long v, float &lo, float &hi) {
    asm("mov.b64 {%0, %1}, %2;" : "=f"(lo), "=f"(hi) : "l"(v));
}

// ---------------- kernel 0a: NCHW -> NHWC transpose of x ----------------
__global__ void transpose_x_kernel(const float* __restrict__ x) {
    __shared__ float tile[32][33];
    int s0 = blockIdx.x * 32;
    int c0 = blockIdx.y * 32;
    int b  = blockIdx.z;
    int tx = threadIdx.x, ty = threadIdx.y;
    #pragma unroll
    for (int i = 0; i < 4; i++) {
        int c = c0 + ty + i * 8;
        tile[ty + i * 8][tx] = x[((size_t)b * CC + c) * SS + s0 + tx];
    }
    __syncthreads();
    #pragma unroll
    for (int i = 0; i < 4; i++) {
        int s = s0 + ty + i * 8;
        g_xt[((size_t)b * SS + s) * CC + c0 + tx] = tile[tx][ty + i * 8];
    }
}

// ---------------- kernel 0b: weight -> bf16 hi/lo swizzled chunk tiles ----------------
__global__ void wprep_kernel(const float* __restrict__ w) {
    int o  = blockIdx.x;        // 0..255
    int ch = blockIdx.y;        // 0..17
    int j  = threadIdx.x;       // 0..63
    int k  = ch >> 1, c0 = (ch & 1) * 64;
    float v = w[(size_t)o * CK + (size_t)(c0 + j) * KK + k];
    __nv_bfloat16 hi = __float2bfloat16_rn(v);
    float rv = v - __bfloat162float(hi);
    __nv_bfloat16 lo = __float2bfloat16_rn(rv);
    int byte = o * 128 + j * 2;
    int sw = byte ^ ((byte >> 3) & 0x70);
    *(__nv_bfloat16*)((char*)g_wbh + (size_t)ch * 32768 + sw) = hi;
    *(__nv_bfloat16*)((char*)g_wbl + (size_t)ch * 32768 + sw) = lo;
}

// ---------------- kernel 1: offset+mask conv (f32x2 packed), emit meta ----------------
__global__ __launch_bounds__(256) void offmask_kernel(
    const float* __restrict__ x,
    const float* __restrict__ ow, const float* __restrict__ ob,
    const float* __restrict__ mw, const float* __restrict__ mb)
{
    __shared__ float  xs[8][18][18];
    __shared__ float2 ws2[8][9][14];   // oc-pairs (28 padded from 27)

    int tx = threadIdx.x, ty = threadIdx.y;
    int tid = ty * 16 + tx;
    int b = blockIdx.z;
    int hb = blockIdx.y * 16, wb = blockIdx.x * 16;
    int ho = hb + ty, wo = wb + tx;

    auto bval = [&](int oc) -> float {
        if (oc < 18) return ob[oc];
        if (oc < 27) return mb[oc - 18];
        return 0.f;
    };
    unsigned long long acc2[14];
    #pragma unroll
    for (int p = 0; p < 14; p++) acc2[p] = pkf2(bval(2 * p), bval(2 * p + 1));

    for (int c0 = 0; c0 < CC; c0 += 8) {
        __syncthreads();
        for (int idx = tid; idx < 8 * 18 * 18; idx += 256) {
            int c = idx / 324;
            int rem = idx - c * 324;
            int r = rem / 18, col = rem - r * 18;
            int gy = hb + r - 1, gx = wb + col - 1;
            float v = 0.f;
            if ((unsigned)gy < (unsigned)HH && (unsigned)gx < (unsigned)WW)
                v = x[(((size_t)b * CC + c0 + c) * HH + gy) * WW + gx];
            xs[c][r][col] = v;
        }
        for (int idx = tid; idx < 8 * 9 * 14; idx += 256) {
            int c = idx / 126;
            int rem = idx - c * 126;
            int t = rem / 14, p = rem - t * 14;
            auto wval = [&](int oc) -> float {
                if (oc < 18) return ow[((size_t)oc * CC + (c0 + c)) * 9 + t];
                if (oc < 27) return mw[((size_t)(oc - 18) * CC + (c0 + c)) * 9 + t];
                return 0.f;
            };
            ws2[c][t][p] = make_float2(wval(2 * p), wval(2 * p + 1));
        }
        __syncthreads();

        #pragma unroll
        for (int c = 0; c < 8; c++) {
            float xv[9];
            #pragma unroll
            for (int t = 0; t < 9; t++) xv[t] = xs[c][ty + t / 3][tx + t % 3];
            #pragma unroll
            for (int t = 0; t < 9; t++) {
                unsigned long long d = dup2(xv[t]);
                #pragma unroll
                for (int p = 0; p < 14; p++)
                    fma2(acc2[p], d, *(const unsigned long long*)&ws2[c][t][p]);
            }
        }
    }

    float acc[28];
    #pragma unroll
    for (int p = 0; p < 14; p++) unpack2(acc2[p], acc[2 * p], acc[2 * p + 1]);

    size_t pix = (size_t)b * SS + (size_t)ho * WW + wo;
    #pragma unroll
    for (int k = 0; k < 9; k++) {
        int kh = k / 3, kw = k % 3;
        float py = (float)(ho + kh - 1) + acc[2 * k];
        float px = (float)(wo + kw - 1) + acc[2 * k + 1];
        float m = 1.f / (1.f + __expf(-acc[18 + k]));

        float y0f = floorf(py), x0f = floorf(px);
        float wy1 = py - y0f, wx1 = px - x0f;
        float wy0 = 1.f - wy1, wx0 = 1.f - wx1;
        int y0 = (int)y0f, x0i = (int)x0f;
        int y1 = y0 + 1, x1 = x0i + 1;
        bool vy0 = (unsigned)y0  < (unsigned)HH;
        bool vy1 = (unsigned)y1  < (unsigned)HH;
        bool vx0 = (unsigned)x0i < (unsigned)WW;
        bool vx1 = (unsigned)x1  < (unsigned)WW;
        int cy0 = min(max(y0, 0), HH - 1), cy1 = min(max(y1, 0), HH - 1);
        int cx0 = min(max(x0i, 0), WW - 1), cx1 = min(max(x1, 0), WW - 1);

        float w00 = (vy0 && vx0) ? wy0 * wx0 * m : 0.f;
        float w01 = (vy0 && vx1) ? wy0 * wx1 * m : 0.f;
        float w10 = (vy1 && vx0) ? wy1 * wx0 * m : 0.f;
        float w11 = (vy1 && vx1) ? wy1 * wx1 * m : 0.f;

        g_mw[(size_t)k * BSS + pix] = make_float4(w00, w01, w10, w11);
        g_mi[(size_t)k * BSS + pix] = make_int4(cy0 * WW + cx0, cy0 * WW + cx1,
                                                cy1 * WW + cx0, cy1 * WW + cx1);
    }
}

// ---------------- kernel 2: deformable gather + mma.sync bf16-split GEMM ----------------
// CTA: 128 px x 128 oc (grid: 576 tiles x 2 oc-halves), 8 warps (4M x 2N),
// warp tile 32x64, 64 fp32 accums/thread, 2 CTAs/SM.
#define SM_MW4   0          // float4[128]
#define SM_MI4   2048       // int4[128]
#define SM_A     4096       // Ah(16384) + Al(16384)
#define SM_B     36864      // 2 bufs x (Bh 16384 + Bl 16384)
#define SM_TOTAL 102400

__global__ __launch_bounds__(256, 2) void deform_mma_kernel(
    float* __restrict__ out, const float* __restrict__ bias)
{
    extern __shared__ char smem[];
    uint32_t sb = smem_u32(smem);
    int tid = threadIdx.x;
    int wid = tid >> 5;
    int lane = tid & 31;

    int tile = blockIdx.x;
    int b = tile / (SS / 128);
    int s0 = (tile - b * (SS / 128)) * 128;
    int ocbase = blockIdx.y * 128;

    float4* s_mw4 = (float4*)(smem + SM_MW4);
    int4*   s_mi4 = (int4*)(smem + SM_MI4);

    // warp geometry: 4 M-quarters x 2 N-halves
    int wm = wid & 3;
    int wn = wid >> 2;
    uint32_t rsel = lane & 15;
    uint32_t csel = (uint32_t)(lane >> 4) * 16u;
    uint32_t xorv = (uint32_t)(lane & 7) * 16u;
    uint32_t aLaneOff = (uint32_t)(wm * 32 + rsel) * 128u;
    uint32_t bLaneOff = (uint32_t)(wn * 64 + rsel) * 128u;

    float acc[64];
    #pragma unroll
    for (int i = 0; i < 64; i++) acc[i] = 0.f;

    int g = tid >> 3, j = tid & 7;
    const float* xb = g_xt + (size_t)b * SS * CC;

    // prefetch B chunk 0 (this CTA's oc half: 16KB hi + 16KB lo)
    {
        const char* gh = (const char*)g_wbh + (size_t)ocbase * 128;
        const char* gl = (const char*)g_wbl + (size_t)ocbase * 128;
        uint32_t bh = sb + SM_B;
        #pragma unroll
        for (int i = 0; i < 4; i++) {
            uint32_t off = (uint32_t)(tid + i * 256) * 16u;
            cp16(bh + off, gh + off);
            cp16(bh + 16384u + off, gl + off);
        }
        asm volatile("cp.async.commit_group;" ::: "memory");
    }

    for (int ch = 0; ch < NCH; ch++) {
        int buf = ch & 1;
        int c0 = (ch & 1) * 64;

        if ((ch & 1) == 0) {
            if (tid < 128) {
                size_t mo = (size_t)(ch >> 1) * BSS + (size_t)b * SS + s0 + tid;
                s_mw4[tid] = g_mw[mo];
                s_mi4[tid] = g_mi[mo];
            }
            __syncthreads();
        }

        // ---- gather A chunk: 128 px x 64 ch -> bf16 hi/lo swizzled ----
        {
            char* ahp = smem + SM_A;
            char* alp = ahp + 16384;
            const float* xc = xb + c0 + j * 4;
            #pragma unroll
            for (int it = 0; it < 4; it++) {
                int p = g + it * 32;
                float4 wv = s_mw4[p];
                int4  iv = s_mi4[p];
                const float* r0p = xc + (size_t)iv.x * CC;
                const float* r1p = xc + (size_t)iv.y * CC;
                const float* r2p = xc + (size_t)iv.z * CC;
                const float* r3p = xc + (size_t)iv.w * CC;
                #pragma unroll
                for (int h = 0; h < 2; h++) {
                    float4 v0 = *(const float4*)(r0p + h * 32);
                    float4 v1 = *(const float4*)(r1p + h * 32);
                    float4 v2 = *(const float4*)(r2p + h * 32);
                    float4 v3 = *(const float4*)(r3p + h * 32);
                    float sv0 = wv.x * v0.x + wv.y * v1.x + wv.z * v2.x + wv.w * v3.x;
                    float sv1 = wv.x * v0.y + wv.y * v1.y + wv.z * v2.y + wv.w * v3.y;
                    float sv2 = wv.x * v0.z + wv.y * v1.z + wv.z * v2.z + wv.w * v3.z;
                    float sv3 = wv.x * v0.w + wv.y * v1.w + wv.z * v2.w + wv.w * v3.w;
                    uint32_t hiA = pk2(sv0, sv1);
                    uint32_t hiB = pk2(sv2, sv3);
                    float hf0 = __uint_as_float(hiA << 16);
                    float hf1 = __uint_as_float(hiA & 0xFFFF0000u);
                    float hf2 = __uint_as_float(hiB << 16);
                    float hf3 = __uint_as_float(hiB & 0xFFFF0000u);
                    uint32_t loA = pk2(sv0 - hf0, sv1 - hf1);
                    uint32_t loB = pk2(sv2 - hf2, sv3 - hf3);
                    int byte = p * 128 + h * 64 + j * 8;
                    int sw = byte ^ ((byte >> 3) & 0x70);
                    *(uint2*)(ahp + sw) = make_uint2(hiA, hiB);
                    *(uint2*)(alp + sw) = make_uint2(loA, loB);
                }
            }
        }

        // prefetch next B chunk
        if (ch + 1 < NCH) {
            const char* gh = (const char*)g_wbh + (size_t)(ch + 1) * 32768 + (size_t)ocbase * 128;
            const char* gl = (const char*)g_wbl + (size_t)(ch + 1) * 32768 + (size_t)ocbase * 128;
            uint32_t bh = sb + SM_B + (uint32_t)((ch + 1) & 1) * 32768u;
            #pragma unroll
            for (int i = 0; i < 4; i++) {
                uint32_t off = (uint32_t)(tid + i * 256) * 16u;
                cp16(bh + off, gh + off);
                cp16(bh + 16384u + off, gl + off);
            }
            asm volatile("cp.async.commit_group;" ::: "memory");
            asm volatile("cp.async.wait_group 1;" ::: "memory");
        } else {
            asm volatile("cp.async.wait_group 0;" ::: "memory");
        }
        __syncthreads();

        // ---- mma: per kstep load AhBh once, reuse across 3 products ----
        uint32_t aT = sb + SM_A;
        uint32_t bT = sb + SM_B + (uint32_t)buf * 32768u;
        #pragma unroll
        for (int s = 0; s < 4; s++) {
            uint32_t colsw = ((uint32_t)(s * 32) + csel) ^ xorv;
            uint32_t aH[2][4], aL[2][4], bH[4][4], bL[4][4];
            #pragma unroll
            for (int mt = 0; mt < 2; mt++)
                ldsm4(aH[mt], aT + aLaneOff + (uint32_t)mt * 2048u + colsw);
            #pragma unroll
            for (int ng = 0; ng < 4; ng++)
                ldsm4(bH[ng], bT + bLaneOff + (uint32_t)ng * 2048u + colsw);
            // Ah * Bh
            #pragma unroll
            for (int mt = 0; mt < 2; mt++)
                #pragma unroll
                for (int ng = 0; ng < 4; ng++) {
                    mma16816(&acc[(mt * 8 + ng * 2) * 4],     aH[mt], bH[ng][0], bH[ng][2]);
                    mma16816(&acc[(mt * 8 + ng * 2 + 1) * 4], aH[mt], bH[ng][1], bH[ng][3]);
                }
            // Al * Bh
            #pragma unroll
            for (int mt = 0; mt < 2; mt++)
                ldsm4(aL[mt], aT + 16384u + aLaneOff + (uint32_t)mt * 2048u + colsw);
            #pragma unroll
            for (int mt = 0; mt < 2; mt++)
                #pragma unroll
                for (int ng = 0; ng < 4; ng++) {
                    mma16816(&acc[(mt * 8 + ng * 2) * 4],     aL[mt], bH[ng][0], bH[ng][2]);
                    mma16816(&acc[(mt * 8 + ng * 2 + 1) * 4], aL[mt], bH[ng][1], bH[ng][3]);
                }
            // Ah * Bl
            #pragma unroll
            for (int ng = 0; ng < 4; ng++)
                ldsm4(bL[ng], bT + 16384u + bLaneOff + (uint32_t)ng * 2048u + colsw);
            #pragma unroll
            for (int mt = 0; mt < 2; mt++)
                #pragma unroll
                for (int ng = 0; ng < 4; ng++) {
                    mma16816(&acc[(mt * 8 + ng * 2) * 4],     aH[mt], bL[ng][0], bL[ng][2]);
                    mma16816(&acc[(mt * 8 + ng * 2 + 1) * 4], aH[mt], bL[ng][1], bL[ng][3]);
                }
        }
        __syncthreads();
    }

    // ---- epilogue: stage 64-oc halves in smem, coalesced store ----
    float* sEp = (float*)(smem + SM_B);
    int r0 = lane >> 2, c0l = (lane & 3) * 2;
    for (int q = 0; q < 2; q++) {
        if (wn == q) {
            #pragma unroll
            for (int mt = 0; mt < 2; mt++) {
                int px = wm * 32 + mt * 16 + r0;
                #pragma unroll
                for (int nn = 0; nn < 8; nn++) {
                    float* a4 = &acc[(mt * 8 + nn) * 4];
                    int ocl = nn * 8 + c0l;
                    sEp[ocl * 132 + px]           = a4[0];
                    sEp[(ocl + 1) * 132 + px]     = a4[1];
                    sEp[ocl * 132 + px + 8]       = a4[2];
                    sEp[(ocl + 1) * 132 + px + 8] = a4[3];
                }
            }
        }
        __syncthreads();
        for (int i = tid; i < 2048; i += 256) {
            int r = i >> 5, c = i & 31;
            float4 v = *(float4*)(sEp + r * 132 + c * 4);
            float bv = __ldg(bias + ocbase + q * 64 + r);
            v.x += bv; v.y += bv; v.z += bv; v.w += bv;
            *(float4*)(out + ((size_t)b * OO + ocbase + q * 64 + r) * SS + s0 + c * 4) = v;
        }
        __syncthreads();
    }
}

// ---------------- launch ----------------
extern "C" void kernel_launch(void* const* d_in, const int* in_sizes, int n_in,
                              void* d_out, int out_size) {
    const float* x    = (const float*)d_in[0];
    const float* ow   = (const float*)d_in[1];
    const float* ob   = (const float*)d_in[2];
    const float* mw   = (const float*)d_in[3];
    const float* mb   = (const float*)d_in[4];
    const float* w    = (const float*)d_in[5];
    const float* bias = (const float*)d_in[6];
    float* out = (float*)d_out;

    transpose_x_kernel<<<dim3(SS / 32, CC / 32, BB), dim3(32, 8)>>>(x);
    wprep_kernel<<<dim3(OO, NCH), 64>>>(w);
    offmask_kernel<<<dim3(WW / 16, HH / 16, BB), dim3(16, 16)>>>(x, ow, ob, mw, mb);

    cudaFuncSetAttribute(deform_mma_kernel,
                         cudaFuncAttributeMaxDynamicSharedMemorySize, SM_TOTAL);
    deform_mma_kernel<<<dim3(BSS / 128, 2), 256, SM_TOTAL>>>(out, bias);
}

// round 6
// speedup vs baseline: 2.4469x; 1.3665x over previous
#include <cuda_runtime.h>
#include <cuda_bf16.h>
#include <cuda_fp16.h>
#include <cstdint>

// Problem constants
#define BB 8
#define CC 128
#define OO 256
#define HH 96
#define WW 96
#define SS (HH*WW)          // 9216
#define KK 9                // 3x3 taps
#define CK (CC*KK)          // 1152
#define BSS (BB*SS)         // 73728
#define NSC 36              // K subchunks of 32 channels (sc = tap*4 + quarter)

// ---------------- static device scratch (no allocs allowed) ----------------
__device__ __align__(16) float g_xt[(size_t)BSS*CC];     // x NHWC
__device__ __align__(16) float4 g_mw[(size_t)KK*BSS];    // corner weights (tap-major)
__device__ __align__(16) int4   g_mi[(size_t)KK*BSS];    // corner indices (tap-major)
__device__ __align__(16) __half g_wh[(size_t)NSC*OO*32]; // fp16 weights, swizzled subchunk tiles

// ---------------- helpers ----------------
__device__ __forceinline__ uint32_t smem_u32(const void* p) {
    uint32_t a;
    asm("{ .reg .u64 t; cvta.to.shared.u64 t, %1; cvt.u32.u64 %0, t; }" : "=r"(a) : "l"(p));
    return a;
}
// pack two fp32 -> f16x2 (lo in low half)
__device__ __forceinline__ uint32_t pkh2(float lo, float hi) {
    uint32_t r;
    asm("cvt.rn.f16x2.f32 %0, %1, %2;" : "=r"(r) : "f"(hi), "f"(lo));
    return r;
}
__device__ __forceinline__ void ldsm4(uint32_t* r, uint32_t addr) {
    asm volatile("ldmatrix.sync.aligned.m8n8.x4.shared.b16 {%0,%1,%2,%3}, [%4];"
                 : "=r"(r[0]), "=r"(r[1]), "=r"(r[2]), "=r"(r[3]) : "r"(addr));
}
__device__ __forceinline__ void mma16816h(float* c, const uint32_t* a, uint32_t b0, uint32_t b1) {
    asm volatile(
        "mma.sync.aligned.m16n8k16.row.col.f32.f16.f16.f32 "
        "{%0,%1,%2,%3}, {%4,%5,%6,%7}, {%8,%9}, {%0,%1,%2,%3};"
        : "+f"(c[0]), "+f"(c[1]), "+f"(c[2]), "+f"(c[3])
        : "r"(a[0]), "r"(a[1]), "r"(a[2]), "r"(a[3]), "r"(b0), "r"(b1));
}
__device__ __forceinline__ void cp16(uint32_t dst, const void* src) {
    asm volatile("cp.async.cg.shared.global [%0], [%1], 16;" :: "r"(dst), "l"(src));
}
// f32x2 packed ops (for offmask)
__device__ __forceinline__ void fma2(unsigned long long &d, unsigned long long a,
                                     unsigned long long b) {
    asm("fma.rn.f32x2 %0, %1, %2, %0;" : "+l"(d) : "l"(a), "l"(b));
}
__device__ __forceinline__ unsigned long long dup2(float v) {
    unsigned long long r;
    asm("mov.b64 %0, {%1, %1};" : "=l"(r) : "f"(v));
    return r;
}
__device__ __forceinline__ unsigned long long pkf2(float lo, float hi) {
    unsigned long long r;
    asm("mov.b64 %0, {%1, %2};" : "=l"(r) : "f"(lo), "f"(hi));
    return r;
}
__device__ __forceinline__ void unpack2(unsigned long long v, float &lo, float &hi) {
    asm("mov.b64 {%0, %1}, %2;" : "=f"(lo), "=f"(hi) : "l"(v));
}

// ---------------- kernel 0a: NCHW -> NHWC transpose of x ----------------
__global__ void transpose_x_kernel(const float* __restrict__ x) {
    __shared__ float tile[32][33];
    int s0 = blockIdx.x * 32;
    int c0 = blockIdx.y * 32;
    int b  = blockIdx.z;
    int tx = threadIdx.x, ty = threadIdx.y;
    #pragma unroll
    for (int i = 0; i < 4; i++) {
        int c = c0 + ty + i * 8;
        tile[ty + i * 8][tx] = x[((size_t)b * CC + c) * SS + s0 + tx];
    }
    __syncthreads();
    #pragma unroll
    for (int i = 0; i < 4; i++) {
        int s = s0 + ty + i * 8;
        g_xt[((size_t)b * SS + s) * CC + c0 + tx] = tile[tx][ty + i * 8];
    }
}

// ---------------- kernel 0b: weight -> fp16 swizzled subchunk tiles ----------------
// subchunk sc: tap k = sc>>2, channels c = (sc&3)*32 + j. Tile [256 oc rows][32 f16],
// 64B rows, swizzle: off ^ ((row&7)<<4).
__global__ void wprep_kernel(const float* __restrict__ w) {
    int o  = blockIdx.x;        // 0..255
    int sc = blockIdx.y;        // 0..35
    int j  = threadIdx.x;       // 0..31
    int k  = sc >> 2, c = (sc & 3) * 32 + j;
    float v = w[(size_t)o * CK + (size_t)c * KK + k];
    int off = o * 64 + j * 2;
    int sw = off ^ ((o & 7) << 4);
    *(__half*)((char*)g_wh + (size_t)sc * 16384 + sw) = __float2half_rn(v);
}

// ---------------- kernel 1: offset+mask conv (f32x2 packed), emit meta ----------------
__global__ __launch_bounds__(256) void offmask_kernel(
    const float* __restrict__ x,
    const float* __restrict__ ow, const float* __restrict__ ob,
    const float* __restrict__ mw, const float* __restrict__ mb)
{
    __shared__ float  xs[8][18][18];
    __shared__ float2 ws2[8][9][14];   // oc-pairs (28 padded from 27)

    int tx = threadIdx.x, ty = threadIdx.y;
    int tid = ty * 16 + tx;
    int b = blockIdx.z;
    int hb = blockIdx.y * 16, wb = blockIdx.x * 16;
    int ho = hb + ty, wo = wb + tx;

    auto bval = [&](int oc) -> float {
        if (oc < 18) return ob[oc];
        if (oc < 27) return mb[oc - 18];
        return 0.f;
    };
    unsigned long long acc2[14];
    #pragma unroll
    for (int p = 0; p < 14; p++) acc2[p] = pkf2(bval(2 * p), bval(2 * p + 1));

    for (int c0 = 0; c0 < CC; c0 += 8) {
        __syncthreads();
        for (int idx = tid; idx < 8 * 18 * 18; idx += 256) {
            int c = idx / 324;
            int rem = idx - c * 324;
            int r = rem / 18, col = rem - r * 18;
            int gy = hb + r - 1, gx = wb + col - 1;
            float v = 0.f;
            if ((unsigned)gy < (unsigned)HH && (unsigned)gx < (unsigned)WW)
                v = x[(((size_t)b * CC + c0 + c) * HH + gy) * WW + gx];
            xs[c][r][col] = v;
        }
        for (int idx = tid; idx < 8 * 9 * 14; idx += 256) {
            int c = idx / 126;
            int rem = idx - c * 126;
            int t = rem / 14, p = rem - t * 14;
            auto wval = [&](int oc) -> float {
                if (oc < 18) return ow[((size_t)oc * CC + (c0 + c)) * 9 + t];
                if (oc < 27) return mw[((size_t)(oc - 18) * CC + (c0 + c)) * 9 + t];
                return 0.f;
            };
            ws2[c][t][p] = make_float2(wval(2 * p), wval(2 * p + 1));
        }
        __syncthreads();

        #pragma unroll
        for (int c = 0; c < 8; c++) {
            float xv[9];
            #pragma unroll
            for (int t = 0; t < 9; t++) xv[t] = xs[c][ty + t / 3][tx + t % 3];
            #pragma unroll
            for (int t = 0; t < 9; t++) {
                unsigned long long d = dup2(xv[t]);
                #pragma unroll
                for (int p = 0; p < 14; p++)
                    fma2(acc2[p], d, *(const unsigned long long*)&ws2[c][t][p]);
            }
        }
    }

    float acc[28];
    #pragma unroll
    for (int p = 0; p < 14; p++) unpack2(acc2[p], acc[2 * p], acc[2 * p + 1]);

    size_t pix = (size_t)b * SS + (size_t)ho * WW + wo;
    #pragma unroll
    for (int k = 0; k < 9; k++) {
        int kh = k / 3, kw = k % 3;
        float py = (float)(ho + kh - 1) + acc[2 * k];
        float px = (float)(wo + kw - 1) + acc[2 * k + 1];
        float m = 1.f / (1.f + __expf(-acc[18 + k]));

        float y0f = floorf(py), x0f = floorf(px);
        float wy1 = py - y0f, wx1 = px - x0f;
        float wy0 = 1.f - wy1, wx0 = 1.f - wx1;
        int y0 = (int)y0f, x0i = (int)x0f;
        int y1 = y0 + 1, x1 = x0i + 1;
        bool vy0 = (unsigned)y0  < (unsigned)HH;
        bool vy1 = (unsigned)y1  < (unsigned)HH;
        bool vx0 = (unsigned)x0i < (unsigned)WW;
        bool vx1 = (unsigned)x1  < (unsigned)WW;
        int cy0 = min(max(y0, 0), HH - 1), cy1 = min(max(y1, 0), HH - 1);
        int cx0 = min(max(x0i, 0), WW - 1), cx1 = min(max(x1, 0), WW - 1);

        float w00 = (vy0 && vx0) ? wy0 * wx0 * m : 0.f;
        float w01 = (vy0 && vx1) ? wy0 * wx1 * m : 0.f;
        float w10 = (vy1 && vx0) ? wy1 * wx0 * m : 0.f;
        float w11 = (vy1 && vx1) ? wy1 * wx1 * m : 0.f;

        g_mw[(size_t)k * BSS + pix] = make_float4(w00, w01, w10, w11);
        g_mi[(size_t)k * BSS + pix] = make_int4(cy0 * WW + cx0, cy0 * WW + cx1,
                                                cy1 * WW + cx0, cy1 * WW + cx1);
    }
}

// ---------------- kernel 2: deformable gather + fp16 mma GEMM ----------------
// One 512-thread CTA per 128-px tile, 256 oc. 16 warps (4M x 4N), warp 32x64.
// K = 36 subchunks of 32ch; A double-buffered (fp16, 64B rows), B triple-buffered cp.async.
#define SM_MW4   0          // float4[128]
#define SM_MI4   2048       // int4[128]
#define SM_A     4096       // 2 x 8192
#define SM_B     20480      // 3 x 16384
#define SM_EP    20480      // epilogue staging reuses B
#define SM_TOTAL 69632

__global__ __launch_bounds__(512, 1) void deform_mma_kernel(
    float* __restrict__ out, const float* __restrict__ bias)
{
    extern __shared__ char smem[];
    uint32_t sb = smem_u32(smem);
    int tid = threadIdx.x;
    int wid = tid >> 5;
    int lane = tid & 31;

    int tile = blockIdx.x;
    int b = tile / (SS / 128);
    int s0 = (tile - b * (SS / 128)) * 128;

    float4* s_mw4 = (float4*)(smem + SM_MW4);
    int4*   s_mi4 = (int4*)(smem + SM_MI4);

    // warp geometry: 4 M-quarters (32 px) x 4 N-quarters (64 oc)
    int wm = wid & 3;
    int wn = wid >> 2;
    uint32_t rsel = lane & 15;
    uint32_t csel = (uint32_t)(lane >> 4) * 16u;
    uint32_t xorv = (rsel & 7) * 16u;
    uint32_t aLin = (uint32_t)(wm * 32 + rsel) * 64u + csel;
    uint32_t bLin = (uint32_t)(wn * 64 + rsel) * 64u + csel;

    float acc[64];
    #pragma unroll
    for (int i = 0; i < 64; i++) acc[i] = 0.f;

    int g = tid >> 3, j = tid & 7;
    const float* xb = g_xt + (size_t)b * SS * CC;

    // prefetch B subchunks 0 and 1 (16KB each, pre-swizzled)
    #pragma unroll
    for (int pc = 0; pc < 2; pc++) {
        const char* gw = (const char*)g_wh + (size_t)pc * 16384;
        uint32_t dst = sb + SM_B + (uint32_t)pc * 16384u;
        #pragma unroll
        for (int i = 0; i < 2; i++) {
            uint32_t off = (uint32_t)(tid + i * 512) * 16u;
            cp16(dst + off, gw + off);
        }
        asm volatile("cp.async.commit_group;" ::: "memory");
    }

    for (int sc = 0; sc < NSC; sc++) {
        // per-tap meta (every 4 subchunks)
        if ((sc & 3) == 0) {
            __syncthreads();
            if (tid < 128) {
                size_t mo = (size_t)(sc >> 2) * BSS + (size_t)b * SS + s0 + tid;
                s_mw4[tid] = g_mw[mo];
                s_mi4[tid] = g_mi[mo];
            }
            __syncthreads();
        }

        // ---- gather A subchunk: 128 px x 32 ch -> fp16, 64B-row swizzled ----
        {
            uint32_t aw = sb + SM_A + (uint32_t)(sc & 1) * 8192u;
            const float* xc = xb + (sc & 3) * 32 + j * 4;
            #pragma unroll
            for (int it = 0; it < 2; it++) {
                int p = g + it * 64;
                float4 wv = s_mw4[p];
                int4  iv = s_mi4[p];
                float4 v0 = *(const float4*)(xc + (size_t)iv.x * CC);
                float4 v1 = *(const float4*)(xc + (size_t)iv.y * CC);
                float4 v2 = *(const float4*)(xc + (size_t)iv.z * CC);
                float4 v3 = *(const float4*)(xc + (size_t)iv.w * CC);
                float sv0 = wv.x * v0.x + wv.y * v1.x + wv.z * v2.x + wv.w * v3.x;
                float sv1 = wv.x * v0.y + wv.y * v1.y + wv.z * v2.y + wv.w * v3.y;
                float sv2 = wv.x * v0.z + wv.y * v1.z + wv.z * v2.z + wv.w * v3.z;
                float sv3 = wv.x * v0.w + wv.y * v1.w + wv.z * v2.w + wv.w * v3.w;
                uint32_t h01 = pkh2(sv0, sv1);
                uint32_t h23 = pkh2(sv2, sv3);
                uint32_t addr = (aw + (uint32_t)p * 64u + (uint32_t)j * 8u)
                                ^ ((uint32_t)(p & 7) << 4);
                asm volatile("st.shared.v2.b32 [%0], {%1,%2};"
                             :: "r"(addr), "r"(h01), "r"(h23));
            }
        }

        // B(sc) must be resident before MMA
        if (sc == NSC - 1) asm volatile("cp.async.wait_group 0;" ::: "memory");
        else               asm volatile("cp.async.wait_group 1;" ::: "memory");
        __syncthreads();

        // prefetch B(sc+2) (overlaps MMA below; safe: all warps past barrier)
        if (sc + 2 < NSC) {
            const char* gw = (const char*)g_wh + (size_t)(sc + 2) * 16384;
            uint32_t dst = sb + SM_B + (uint32_t)((sc + 2) % 3) * 16384u;
            #pragma unroll
            for (int i = 0; i < 2; i++) {
                uint32_t off = (uint32_t)(tid + i * 512) * 16u;
                cp16(dst + off, gw + off);
            }
            asm volatile("cp.async.commit_group;" ::: "memory");
        }

        // ---- MMA: 2 ksteps x (2 m-tiles x 4 n-groups) ----
        {
            uint32_t aT = sb + SM_A + (uint32_t)(sc & 1) * 8192u;
            uint32_t bT = sb + SM_B + (uint32_t)(sc % 3) * 16384u;
            #pragma unroll
            for (int t = 0; t < 2; t++) {
                uint32_t aF[2][4], bF[4][4];
                #pragma unroll
                for (int mt = 0; mt < 2; mt++)
                    ldsm4(aF[mt], (aT + aLin + (uint32_t)mt * 1024u + (uint32_t)t * 32u) ^ xorv);
                #pragma unroll
                for (int ng = 0; ng < 4; ng++)
                    ldsm4(bF[ng], (bT + bLin + (uint32_t)ng * 1024u + (uint32_t)t * 32u) ^ xorv);
                #pragma unroll
                for (int mt = 0; mt < 2; mt++) {
                    #pragma unroll
                    for (int ng = 0; ng < 4; ng++) {
                        mma16816h(&acc[(mt * 8 + ng * 2) * 4],     aF[mt], bF[ng][0], bF[ng][2]);
                        mma16816h(&acc[(mt * 8 + ng * 2 + 1) * 4], aF[mt], bF[ng][1], bF[ng][3]);
                    }
                }
            }
        }
    }
    __syncthreads();

    // ---- epilogue: stage 64-oc quarters in smem, coalesced store ----
    float* sEp = (float*)(smem + SM_EP);
    int r0 = lane >> 2, c0l = (lane & 3) * 2;
    for (int q = 0; q < 4; q++) {
        if (wn == q) {
            #pragma unroll
            for (int mt = 0; mt < 2; mt++) {
                int px = wm * 32 + mt * 16 + r0;
                #pragma unroll
                for (int nn = 0; nn < 8; nn++) {
                    float* a4 = &acc[(mt * 8 + nn) * 4];
                    int ocl = nn * 8 + c0l;
                    sEp[ocl * 132 + px]           = a4[0];
                    sEp[(ocl + 1) * 132 + px]     = a4[1];
                    sEp[ocl * 132 + px + 8]       = a4[2];
                    sEp[(ocl + 1) * 132 + px + 8] = a4[3];
                }
            }
        }
        __syncthreads();
        for (int i = tid; i < 2048; i += 512) {
            int r = i >> 5, c = i & 31;
            float4 v = *(float4*)(sEp + r * 132 + c * 4);
            float bv = __ldg(bias + q * 64 + r);
            v.x += bv; v.y += bv; v.z += bv; v.w += bv;
            *(float4*)(out + ((size_t)b * OO + q * 64 + r) * SS + s0 + c * 4) = v;
        }
        __syncthreads();
    }
}

// ---------------- launch ----------------
extern "C" void kernel_launch(void* const* d_in, const int* in_sizes, int n_in,
                              void* d_out, int out_size) {
    const float* x    = (const float*)d_in[0];
    const float* ow   = (const float*)d_in[1];
    const float* ob   = (const float*)d_in[2];
    const float* mw   = (const float*)d_in[3];
    const float* mb   = (const float*)d_in[4];
    const float* w    = (const float*)d_in[5];
    const float* bias = (const float*)d_in[6];
    float* out = (float*)d_out;

    transpose_x_kernel<<<dim3(SS / 32, CC / 32, BB), dim3(32, 8)>>>(x);
    wprep_kernel<<<dim3(OO, NSC), 32>>>(w);
    offmask_kernel<<<dim3(WW / 16, HH / 16, BB), dim3(16, 16)>>>(x, ow, ob, mw, mb);

    cudaFuncSetAttribute(deform_mma_kernel,
                         cudaFuncAttributeMaxDynamicSharedMemorySize, SM_TOTAL);
    deform_mma_kernel<<<BSS / 128, 512, SM_TOTAL>>>(out, bias);
}

// round 7
// speedup vs baseline: 2.7370x; 1.1185x over previous
#include <cuda_runtime.h>
#include <cuda_bf16.h>
#include <cuda_fp16.h>
#include <cstdint>

// Problem constants
#define BB 8
#define CC 128
#define OO 256
#define HH 96
#define WW 96
#define SS (HH*WW)          // 9216
#define KK 9                // 3x3 taps
#define CK (CC*KK)          // 1152
#define BSS (BB*SS)         // 73728
#define NSC 36              // K subchunks of 32 channels (sc = tap*4 + quarter)

// ---------------- static device scratch (no allocs allowed) ----------------
__device__ __align__(16) float g_xt[(size_t)BSS*CC];     // x NHWC
__device__ __align__(16) float4 g_mw[(size_t)KK*BSS];    // corner weights (tap-major)
__device__ __align__(16) int4   g_mi[(size_t)KK*BSS];    // corner indices (tap-major)
__device__ __align__(16) __half g_wh[(size_t)NSC*OO*32]; // fp16 weights, swizzled subchunk tiles

// ---------------- helpers ----------------
__device__ __forceinline__ uint32_t smem_u32(const void* p) {
    uint32_t a;
    asm("{ .reg .u64 t; cvta.to.shared.u64 t, %1; cvt.u32.u64 %0, t; }" : "=r"(a) : "l"(p));
    return a;
}
// pack two fp32 -> f16x2 (lo in low half)
__device__ __forceinline__ uint32_t pkh2(float lo, float hi) {
    uint32_t r;
    asm("cvt.rn.f16x2.f32 %0, %1, %2;" : "=r"(r) : "f"(hi), "f"(lo));
    return r;
}
__device__ __forceinline__ void ldsm4(uint32_t* r, uint32_t addr) {
    asm volatile("ldmatrix.sync.aligned.m8n8.x4.shared.b16 {%0,%1,%2,%3}, [%4];"
                 : "=r"(r[0]), "=r"(r[1]), "=r"(r[2]), "=r"(r[3]) : "r"(addr));
}
__device__ __forceinline__ void mma16816h(float* c, const uint32_t* a, uint32_t b0, uint32_t b1) {
    asm volatile(
        "mma.sync.aligned.m16n8k16.row.col.f32.f16.f16.f32 "
        "{%0,%1,%2,%3}, {%4,%5,%6,%7}, {%8,%9}, {%0,%1,%2,%3};"
        : "+f"(c[0]), "+f"(c[1]), "+f"(c[2]), "+f"(c[3])
        : "r"(a[0]), "r"(a[1]), "r"(a[2]), "r"(a[3]), "r"(b0), "r"(b1));
}
__device__ __forceinline__ void cp16(uint32_t dst, const void* src) {
    asm volatile("cp.async.cg.shared.global [%0], [%1], 16;" :: "r"(dst), "l"(src));
}
// 4-byte cp.async with zero-fill when srcsize==0 (address must still be valid)
__device__ __forceinline__ void cp4z(uint32_t dst, const void* src, uint32_t srcsize) {
    asm volatile("cp.async.ca.shared.global [%0], [%1], 4, %2;"
                 :: "r"(dst), "l"(src), "r"(srcsize));
}
// f32x2 packed ops (for offmask)
__device__ __forceinline__ void fma2(unsigned long long &d, unsigned long long a,
                                     unsigned long long b) {
    asm("fma.rn.f32x2 %0, %1, %2, %0;" : "+l"(d) : "l"(a), "l"(b));
}
__device__ __forceinline__ unsigned long long dup2(float v) {
    unsigned long long r;
    asm("mov.b64 %0, {%1, %1};" : "=l"(r) : "f"(v));
    return r;
}
__device__ __forceinline__ unsigned long long pkf2(float lo, float hi) {
    unsigned long long r;
    asm("mov.b64 %0, {%1, %2};" : "=l"(r) : "f"(lo), "f"(hi));
    return r;
}
__device__ __forceinline__ void unpack2(unsigned long long v, float &lo, float &hi) {
    asm("mov.b64 {%0, %1}, %2;" : "=f"(lo), "=f"(hi) : "l"(v));
}

// ---------------- kernel 0a: NCHW -> NHWC transpose of x ----------------
__global__ void transpose_x_kernel(const float* __restrict__ x) {
    __shared__ float tile[32][33];
    int s0 = blockIdx.x * 32;
    int c0 = blockIdx.y * 32;
    int b  = blockIdx.z;
    int tx = threadIdx.x, ty = threadIdx.y;
    #pragma unroll
    for (int i = 0; i < 4; i++) {
        int c = c0 + ty + i * 8;
        tile[ty + i * 8][tx] = x[((size_t)b * CC + c) * SS + s0 + tx];
    }
    __syncthreads();
    #pragma unroll
    for (int i = 0; i < 4; i++) {
        int s = s0 + ty + i * 8;
        g_xt[((size_t)b * SS + s) * CC + c0 + tx] = tile[tx][ty + i * 8];
    }
}

// ---------------- kernel 0b: weight -> fp16 swizzled subchunk tiles ----------------
__global__ void wprep_kernel(const float* __restrict__ w) {
    int o  = blockIdx.x;        // 0..255
    int sc = blockIdx.y;        // 0..35
    int j  = threadIdx.x;       // 0..31
    int k  = sc >> 2, c = (sc & 3) * 32 + j;
    float v = w[(size_t)o * CK + (size_t)c * KK + k];
    int off = o * 64 + j * 2;
    int sw = off ^ ((o & 7) << 4);
    *(__half*)((char*)g_wh + (size_t)sc * 16384 + sw) = __float2half_rn(v);
}

// ---------------- kernel 1: offset+mask conv, cp.async double-buffered ----------------
__global__ __launch_bounds__(256) void offmask_kernel(
    const float* __restrict__ x,
    const float* __restrict__ ow, const float* __restrict__ ob,
    const float* __restrict__ mw, const float* __restrict__ mb)
{
    __shared__ float  xs2[2][8][18][18];
    __shared__ float2 ws2[2][8][9][14];   // oc-pairs (28 padded from 27)

    int tx = threadIdx.x, ty = threadIdx.y;
    int tid = ty * 16 + tx;
    int b = blockIdx.z;
    int hb = blockIdx.y * 16, wb = blockIdx.x * 16;
    int ho = hb + ty, wo = wb + tx;

    uint32_t xsA = smem_u32(&xs2[0][0][0][0]);
    uint32_t wsA = smem_u32(&ws2[0][0][0][0]);

    auto issue_chunk = [&](int c0, int buf) {
        // xs: 8 ch x 18x18 halo tile (zero-padded via src-size 0)
        for (int idx = tid; idx < 8 * 18 * 18; idx += 256) {
            int c = idx / 324;
            int rem = idx - c * 324;
            int r = rem / 18, col = rem - r * 18;
            int gy = hb + r - 1, gx = wb + col - 1;
            uint32_t vld = ((unsigned)gy < (unsigned)HH && (unsigned)gx < (unsigned)WW) ? 4u : 0u;
            int gyc = min(max(gy, 0), HH - 1), gxc = min(max(gx, 0), WW - 1);
            const float* src = x + (((size_t)b * CC + c0 + c) * HH + gyc) * WW + gxc;
            cp4z(xsA + (uint32_t)buf * 10368u + (uint32_t)idx * 4u, src, vld);
        }
        // ws: 8 ch x 9 taps x 14 oc-pairs (2 scalars each)
        for (int idx = tid; idx < 8 * 9 * 14 * 2; idx += 256) {
            int pr = idx >> 1, hf = idx & 1;
            int c = pr / 126;
            int rem = pr - c * 126;
            int t = rem / 14, p = rem - t * 14;
            int oc = 2 * p + hf;
            uint32_t vld = (oc < 27) ? 4u : 0u;
            const float* src;
            if (oc < 18)      src = ow + ((size_t)oc * CC + (c0 + c)) * 9 + t;
            else if (oc < 27) src = mw + ((size_t)(oc - 18) * CC + (c0 + c)) * 9 + t;
            else              src = ow;   // valid dummy address, zero-filled
            cp4z(wsA + (uint32_t)buf * 8064u + (uint32_t)pr * 8u + (uint32_t)hf * 4u, src, vld);
        }
        asm volatile("cp.async.commit_group;" ::: "memory");
    };

    auto bval = [&](int oc) -> float {
        if (oc < 18) return ob[oc];
        if (oc < 27) return mb[oc - 18];
        return 0.f;
    };
    unsigned long long acc2[14];
    #pragma unroll
    for (int p = 0; p < 14; p++) acc2[p] = pkf2(bval(2 * p), bval(2 * p + 1));

    issue_chunk(0, 0);

    for (int blk = 0; blk < 16; blk++) {
        int buf = blk & 1;
        asm volatile("cp.async.wait_group 0;" ::: "memory");
        __syncthreads();
        if (blk + 1 < 16) issue_chunk((blk + 1) * 8, buf ^ 1);

        #pragma unroll
        for (int c = 0; c < 8; c++) {
            float xv[9];
            #pragma unroll
            for (int t = 0; t < 9; t++) xv[t] = xs2[buf][c][ty + t / 3][tx + t % 3];
            #pragma unroll
            for (int t = 0; t < 9; t++) {
                unsigned long long d = dup2(xv[t]);
                #pragma unroll
                for (int p = 0; p < 14; p++)
                    fma2(acc2[p], d, *(const unsigned long long*)&ws2[buf][c][t][p]);
            }
        }
        __syncthreads();
    }

    float acc[28];
    #pragma unroll
    for (int p = 0; p < 14; p++) unpack2(acc2[p], acc[2 * p], acc[2 * p + 1]);

    size_t pix = (size_t)b * SS + (size_t)ho * WW + wo;
    #pragma unroll
    for (int k = 0; k < 9; k++) {
        int kh = k / 3, kw = k % 3;
        float py = (float)(ho + kh - 1) + acc[2 * k];
        float px = (float)(wo + kw - 1) + acc[2 * k + 1];
        float m = 1.f / (1.f + __expf(-acc[18 + k]));

        float y0f = floorf(py), x0f = floorf(px);
        float wy1 = py - y0f, wx1 = px - x0f;
        float wy0 = 1.f - wy1, wx0 = 1.f - wx1;
        int y0 = (int)y0f, x0i = (int)x0f;
        int y1 = y0 + 1, x1 = x0i + 1;
        bool vy0 = (unsigned)y0  < (unsigned)HH;
        bool vy1 = (unsigned)y1  < (unsigned)HH;
        bool vx0 = (unsigned)x0i < (unsigned)WW;
        bool vx1 = (unsigned)x1  < (unsigned)WW;
        int cy0 = min(max(y0, 0), HH - 1), cy1 = min(max(y1, 0), HH - 1);
        int cx0 = min(max(x0i, 0), WW - 1), cx1 = min(max(x1, 0), WW - 1);

        float w00 = (vy0 && vx0) ? wy0 * wx0 * m : 0.f;
        float w01 = (vy0 && vx1) ? wy0 * wx1 * m : 0.f;
        float w10 = (vy1 && vx0) ? wy1 * wx0 * m : 0.f;
        float w11 = (vy1 && vx1) ? wy1 * wx1 * m : 0.f;

        g_mw[(size_t)k * BSS + pix] = make_float4(w00, w01, w10, w11);
        g_mi[(size_t)k * BSS + pix] = make_int4(cy0 * WW + cx0, cy0 * WW + cx1,
                                                cy1 * WW + cx0, cy1 * WW + cx1);
    }
}

// ---------------- kernel 2: deformable gather + fp16 mma GEMM ----------------
// CTA: 64 px x 256 oc, 256 threads, 8 warps (2M x 4N), warp 32x64, 2 CTAs/SM.
// All 9 taps' meta loaded once; ONE barrier per subchunk.
#define DSM_MW   0          // float4[9*64]
#define DSM_MI   9216       // int4[9*64]
#define DSM_A    18432      // 2 x 4096
#define DSM_B    26624      // 3 x 16384
#define DSM_EP   26624      // epilogue staging reuses B
#define DSM_TOT  75776

__global__ __launch_bounds__(256, 2) void deform_mma_kernel(
    float* __restrict__ out, const float* __restrict__ bias)
{
    extern __shared__ char smem[];
    uint32_t sb = smem_u32(smem);
    int tid = threadIdx.x;
    int wid = tid >> 5;
    int lane = tid & 31;

    int tile = blockIdx.x;
    int b = tile / (SS / 64);
    int s0 = (tile - b * (SS / 64)) * 64;

    float4* s_mw4 = (float4*)(smem + DSM_MW);
    int4*   s_mi4 = (int4*)(smem + DSM_MI);

    // load ALL 9 taps' meta for this 64-px tile (one-time)
    for (int i = tid; i < 576; i += 256) {
        size_t mo = (size_t)(i >> 6) * BSS + (size_t)b * SS + s0 + (i & 63);
        s_mw4[i] = g_mw[mo];
        s_mi4[i] = g_mi[mo];
    }

    // prefetch B subchunks 0 and 1 (16KB each, pre-swizzled)
    #pragma unroll
    for (int pc = 0; pc < 2; pc++) {
        const char* gw = (const char*)g_wh + (size_t)pc * 16384;
        uint32_t dst = sb + DSM_B + (uint32_t)pc * 16384u;
        #pragma unroll
        for (int i = 0; i < 4; i++) {
            uint32_t off = (uint32_t)(tid + i * 256) * 16u;
            cp16(dst + off, gw + off);
        }
        asm volatile("cp.async.commit_group;" ::: "memory");
    }
    __syncthreads();   // meta visible to all

    // warp geometry: 2 M-halves (32 px) x 4 N-quarters (64 oc)
    int wm = wid & 1;
    int wn = wid >> 1;
    uint32_t rsel = lane & 15;
    uint32_t csel = (uint32_t)(lane >> 4) * 16u;
    uint32_t xorv = (rsel & 7) * 16u;
    uint32_t aLin = (uint32_t)(wm * 32 + rsel) * 64u + csel;
    uint32_t bLin = (uint32_t)(wn * 64 + rsel) * 64u + csel;

    float acc[64];
    #pragma unroll
    for (int i = 0; i < 64; i++) acc[i] = 0.f;

    int g = tid >> 3, j = tid & 7;     // g: 0..31 pixel group, j: channel quarter
    const float* xb = g_xt + (size_t)b * SS * CC;

    for (int sc = 0; sc < NSC; sc++) {
        int tap = sc >> 2;

        // ---- gather A subchunk: 64 px x 32 ch -> fp16, 64B-row swizzled ----
        {
            uint32_t aw = sb + DSM_A + (uint32_t)(sc & 1) * 4096u;
            const float* xc = xb + (sc & 3) * 32 + j * 4;
            #pragma unroll
            for (int it = 0; it < 2; it++) {
                int p = g + it * 32;
                float4 wv = s_mw4[tap * 64 + p];
                int4  iv = s_mi4[tap * 64 + p];
                float4 v0 = *(const float4*)(xc + (size_t)iv.x * CC);
                float4 v1 = *(const float4*)(xc + (size_t)iv.y * CC);
                float4 v2 = *(const float4*)(xc + (size_t)iv.z * CC);
                float4 v3 = *(const float4*)(xc + (size_t)iv.w * CC);
                float sv0 = wv.x * v0.x + wv.y * v1.x + wv.z * v2.x + wv.w * v3.x;
                float sv1 = wv.x * v0.y + wv.y * v1.y + wv.z * v2.y + wv.w * v3.y;
                float sv2 = wv.x * v0.z + wv.y * v1.z + wv.z * v2.z + wv.w * v3.z;
                float sv3 = wv.x * v0.w + wv.y * v1.w + wv.z * v2.w + wv.w * v3.w;
                uint32_t h01 = pkh2(sv0, sv1);
                uint32_t h23 = pkh2(sv2, sv3);
                uint32_t addr = (aw + (uint32_t)p * 64u + (uint32_t)j * 8u)
                                ^ ((uint32_t)(p & 7) << 4);
                asm volatile("st.shared.v2.b32 [%0], {%1,%2};"
                             :: "r"(addr), "r"(h01), "r"(h23));
            }
        }

        // B(sc) must be resident before MMA
        if (sc == NSC - 1) asm volatile("cp.async.wait_group 0;" ::: "memory");
        else               asm volatile("cp.async.wait_group 1;" ::: "memory");
        __syncthreads();   // the ONLY barrier per subchunk

        // prefetch B(sc+2) (safe: all warps past barrier => MMA(sc-1) done)
        if (sc + 2 < NSC) {
            const char* gw = (const char*)g_wh + (size_t)(sc + 2) * 16384;
            uint32_t dst = sb + DSM_B + (uint32_t)((sc + 2) % 3) * 16384u;
            #pragma unroll
            for (int i = 0; i < 4; i++) {
                uint32_t off = (uint32_t)(tid + i * 256) * 16u;
                cp16(dst + off, gw + off);
            }
            asm volatile("cp.async.commit_group;" ::: "memory");
        }

        // ---- MMA: 2 ksteps x (2 m-tiles x 4 n-groups) ----
        {
            uint32_t aT = sb + DSM_A + (uint32_t)(sc & 1) * 4096u;
            uint32_t bT = sb + DSM_B + (uint32_t)(sc % 3) * 16384u;
            #pragma unroll
            for (int t = 0; t < 2; t++) {
                uint32_t aF[2][4], bF[4][4];
                #pragma unroll
                for (int mt = 0; mt < 2; mt++)
                    ldsm4(aF[mt], (aT + aLin + (uint32_t)mt * 1024u + (uint32_t)t * 32u) ^ xorv);
                #pragma unroll
                for (int ng = 0; ng < 4; ng++)
                    ldsm4(bF[ng], (bT + bLin + (uint32_t)ng * 1024u + (uint32_t)t * 32u) ^ xorv);
                #pragma unroll
                for (int mt = 0; mt < 2; mt++) {
                    #pragma unroll
                    for (int ng = 0; ng < 4; ng++) {
                        mma16816h(&acc[(mt * 8 + ng * 2) * 4],     aF[mt], bF[ng][0], bF[ng][2]);
                        mma16816h(&acc[(mt * 8 + ng * 2 + 1) * 4], aF[mt], bF[ng][1], bF[ng][3]);
                    }
                }
            }
        }
    }
    __syncthreads();

    // ---- epilogue: stage 64-oc quarters in smem, coalesced store ----
    float* sEp = (float*)(smem + DSM_EP);
    int r0 = lane >> 2, c0l = (lane & 3) * 2;
    for (int q = 0; q < 4; q++) {
        if (wn == q) {
            #pragma unroll
            for (int mt = 0; mt < 2; mt++) {
                int px = wm * 32 + mt * 16 + r0;
                #pragma unroll
                for (int nn = 0; nn < 8; nn++) {
                    float* a4 = &acc[(mt * 8 + nn) * 4];
                    int ocl = nn * 8 + c0l;
                    sEp[ocl * 68 + px]          = a4[0];
                    sEp[(ocl + 1) * 68 + px]    = a4[1];
                    sEp[ocl * 68 + px + 8]      = a4[2];
                    sEp[(ocl + 1) * 68 + px + 8]= a4[3];
                }
            }
        }
        __syncthreads();
        for (int i = tid; i < 1024; i += 256) {
            int r = i >> 4, c = i & 15;
            float4 v = *(float4*)(sEp + r * 68 + c * 4);
            float bv = __ldg(bias + q * 64 + r);
            v.x += bv; v.y += bv; v.z += bv; v.w += bv;
            *(float4*)(out + ((size_t)b * OO + q * 64 + r) * SS + s0 + c * 4) = v;
        }
        __syncthreads();
    }
}

// ---------------- launch ----------------
extern "C" void kernel_launch(void* const* d_in, const int* in_sizes, int n_in,
                              void* d_out, int out_size) {
    const float* x    = (const float*)d_in[0];
    const float* ow   = (const float*)d_in[1];
    const float* ob   = (const float*)d_in[2];
    const float* mw   = (const float*)d_in[3];
    const float* mb   = (const float*)d_in[4];
    const float* w    = (const float*)d_in[5];
    const float* bias = (const float*)d_in[6];
    float* out = (float*)d_out;

    transpose_x_kernel<<<dim3(SS / 32, CC / 32, BB), dim3(32, 8)>>>(x);
    wprep_kernel<<<dim3(OO, NSC), 32>>>(w);
    offmask_kernel<<<dim3(WW / 16, HH / 16, BB), dim3(16, 16)>>>(x, ow, ob, mw, mb);

    cudaFuncSetAttribute(deform_mma_kernel,
                         cudaFuncAttributeMaxDynamicSharedMemorySize, DSM_TOT);
    deform_mma_kernel<<<BSS / 64, 256, DSM_TOT>>>(out, bias);
}

// round 8
// speedup vs baseline: 2.9430x; 1.0752x over previous
#include <cuda_runtime.h>
#include <cuda_bf16.h>
#include <cuda_fp16.h>
#include <cstdint>

// Problem constants
#define BB 8
#define CC 128
#define OO 256
#define HH 96
#define WW 96
#define SS (HH*WW)          // 9216
#define KK 9                // 3x3 taps
#define CK (CC*KK)          // 1152
#define BSS (BB*SS)         // 73728
#define NCH 18              // K chunks of 64 channels (ch = tap*2 + half)

// ---------------- static device scratch (no allocs allowed) ----------------
__device__ __align__(16) float g_xt[(size_t)BSS*CC];     // x NHWC (written by offmask)
__device__ __align__(16) float4 g_mw[(size_t)KK*BSS];    // corner weights (tap-major)
__device__ __align__(16) int4   g_mi[(size_t)KK*BSS];    // corner indices (tap-major)
__device__ __align__(16) __half g_wh[(size_t)NCH*OO*64]; // fp16 weights, swizzled chunk tiles

// ---------------- helpers ----------------
__device__ __forceinline__ uint32_t smem_u32(const void* p) {
    uint32_t a;
    asm("{ .reg .u64 t; cvta.to.shared.u64 t, %1; cvt.u32.u64 %0, t; }" : "=r"(a) : "l"(p));
    return a;
}
// pack two fp32 -> f16x2 (lo in low half)
__device__ __forceinline__ uint32_t pkh2(float lo, float hi) {
    uint32_t r;
    asm("cvt.rn.f16x2.f32 %0, %1, %2;" : "=r"(r) : "f"(hi), "f"(lo));
    return r;
}
__device__ __forceinline__ void ldsm4(uint32_t* r, uint32_t addr) {
    asm volatile("ldmatrix.sync.aligned.m8n8.x4.shared.b16 {%0,%1,%2,%3}, [%4];"
                 : "=r"(r[0]), "=r"(r[1]), "=r"(r[2]), "=r"(r[3]) : "r"(addr));
}
__device__ __forceinline__ void mma16816h(float* c, const uint32_t* a, uint32_t b0, uint32_t b1) {
    asm volatile(
        "mma.sync.aligned.m16n8k16.row.col.f32.f16.f16.f32 "
        "{%0,%1,%2,%3}, {%4,%5,%6,%7}, {%8,%9}, {%0,%1,%2,%3};"
        : "+f"(c[0]), "+f"(c[1]), "+f"(c[2]), "+f"(c[3])
        : "r"(a[0]), "r"(a[1]), "r"(a[2]), "r"(a[3]), "r"(b0), "r"(b1));
}
__device__ __forceinline__ void cp16(uint32_t dst, const void* src) {
    asm volatile("cp.async.cg.shared.global [%0], [%1], 16;" :: "r"(dst), "l"(src));
}
// 4-byte cp.async with zero-fill when srcsize==0 (address must still be valid)
__device__ __forceinline__ void cp4z(uint32_t dst, const void* src, uint32_t srcsize) {
    asm volatile("cp.async.ca.shared.global [%0], [%1], 4, %2;"
                 :: "r"(dst), "l"(src), "r"(srcsize));
}
// f32x2 packed ops (for offmask)
__device__ __forceinline__ void fma2(unsigned long long &d, unsigned long long a,
                                     unsigned long long b) {
    asm("fma.rn.f32x2 %0, %1, %2, %0;" : "+l"(d) : "l"(a), "l"(b));
}
__device__ __forceinline__ unsigned long long dup2(float v) {
    unsigned long long r;
    asm("mov.b64 %0, {%1, %1};" : "=l"(r) : "f"(v));
    return r;
}
__device__ __forceinline__ unsigned long long pkf2(float lo, float hi) {
    unsigned long long r;
    asm("mov.b64 %0, {%1, %2};" : "=l"(r) : "f"(lo), "f"(hi));
    return r;
}
__device__ __forceinline__ void unpack2(unsigned long long v, float &lo, float &hi) {
    asm("mov.b64 {%0, %1}, %2;" : "=f"(lo), "=f"(hi) : "l"(v));
}

// ---------------- kernel 0: weight -> fp16 swizzled chunk tiles ----------------
// chunk ch: tap k = ch>>1, channels c = (ch&1)*64 + j. Tile [256 oc rows][64 f16],
// 128B rows, SW128: off ^ ((o&7)<<4).
__global__ void wprep_kernel(const float* __restrict__ w) {
    int o  = blockIdx.x;        // 0..255
    int ch = blockIdx.y;        // 0..17
    int j  = threadIdx.x;       // 0..63
    int k  = ch >> 1, c = (ch & 1) * 64 + j;
    float v = w[(size_t)o * CK + (size_t)c * KK + k];
    int off = o * 128 + j * 2;
    int sw = off ^ ((o & 7) << 4);
    *(__half*)((char*)g_wh + (size_t)ch * 32768 + sw) = __float2half_rn(v);
}

// ---------------- kernel 1: offset+mask conv + NHWC transpose fused ----------------
__global__ __launch_bounds__(256) void offmask_kernel(
    const float* __restrict__ x,
    const float* __restrict__ ow, const float* __restrict__ ob,
    const float* __restrict__ mw, const float* __restrict__ mb)
{
    __shared__ float  xs2[2][8][18][18];
    __shared__ float2 ws2[2][8][9][14];   // oc-pairs (28 padded from 27)

    int tx = threadIdx.x, ty = threadIdx.y;
    int tid = ty * 16 + tx;
    int b = blockIdx.z;
    int hb = blockIdx.y * 16, wb = blockIdx.x * 16;
    int ho = hb + ty, wo = wb + tx;

    uint32_t xsA = smem_u32(&xs2[0][0][0][0]);
    uint32_t wsA = smem_u32(&ws2[0][0][0][0]);

    auto issue_chunk = [&](int c0, int buf) {
        for (int idx = tid; idx < 8 * 18 * 18; idx += 256) {
            int c = idx / 324;
            int rem = idx - c * 324;
            int r = rem / 18, col = rem - r * 18;
            int gy = hb + r - 1, gx = wb + col - 1;
            uint32_t vld = ((unsigned)gy < (unsigned)HH && (unsigned)gx < (unsigned)WW) ? 4u : 0u;
            int gyc = min(max(gy, 0), HH - 1), gxc = min(max(gx, 0), WW - 1);
            const float* src = x + (((size_t)b * CC + c0 + c) * HH + gyc) * WW + gxc;
            cp4z(xsA + (uint32_t)buf * 10368u + (uint32_t)idx * 4u, src, vld);
        }
        for (int idx = tid; idx < 8 * 9 * 14 * 2; idx += 256) {
            int pr = idx >> 1, hf = idx & 1;
            int c = pr / 126;
            int rem = pr - c * 126;
            int t = rem / 14, p = rem - t * 14;
            int oc = 2 * p + hf;
            uint32_t vld = (oc < 27) ? 4u : 0u;
            const float* src;
            if (oc < 18)      src = ow + ((size_t)oc * CC + (c0 + c)) * 9 + t;
            else if (oc < 27) src = mw + ((size_t)(oc - 18) * CC + (c0 + c)) * 9 + t;
            else              src = ow;   // valid dummy address, zero-filled
            cp4z(wsA + (uint32_t)buf * 8064u + (uint32_t)pr * 8u + (uint32_t)hf * 4u, src, vld);
        }
        asm volatile("cp.async.commit_group;" ::: "memory");
    };

    auto bval = [&](int oc) -> float {
        if (oc < 18) return ob[oc];
        if (oc < 27) return mb[oc - 18];
        return 0.f;
    };
    unsigned long long acc2[14];
    #pragma unroll
    for (int p = 0; p < 14; p++) acc2[p] = pkf2(bval(2 * p), bval(2 * p + 1));

    issue_chunk(0, 0);

    size_t xtbase = ((size_t)b * SS + (size_t)ho * WW + wo) * CC;

    for (int blk = 0; blk < 16; blk++) {
        int buf = blk & 1;
        asm volatile("cp.async.wait_group 0;" ::: "memory");
        __syncthreads();
        if (blk + 1 < 16) issue_chunk((blk + 1) * 8, buf ^ 1);

        float xv8[8][9];
        #pragma unroll
        for (int c = 0; c < 8; c++) {
            #pragma unroll
            for (int t = 0; t < 9; t++) xv8[c][t] = xs2[buf][c][ty + t / 3][tx + t % 3];
        }
        // fused NHWC transpose write (center tap t=4 is the pixel itself)
        {
            float4 f0 = make_float4(xv8[0][4], xv8[1][4], xv8[2][4], xv8[3][4]);
            float4 f1 = make_float4(xv8[4][4], xv8[5][4], xv8[6][4], xv8[7][4]);
            *(float4*)(g_xt + xtbase + blk * 8)     = f0;
            *(float4*)(g_xt + xtbase + blk * 8 + 4) = f1;
        }
        #pragma unroll
        for (int c = 0; c < 8; c++) {
            #pragma unroll
            for (int t = 0; t < 9; t++) {
                unsigned long long d = dup2(xv8[c][t]);
                #pragma unroll
                for (int p = 0; p < 14; p++)
                    fma2(acc2[p], d, *(const unsigned long long*)&ws2[buf][c][t][p]);
            }
        }
        __syncthreads();
    }

    float acc[28];
    #pragma unroll
    for (int p = 0; p < 14; p++) unpack2(acc2[p], acc[2 * p], acc[2 * p + 1]);

    size_t pix = (size_t)b * SS + (size_t)ho * WW + wo;
    #pragma unroll
    for (int k = 0; k < 9; k++) {
        int kh = k / 3, kw = k % 3;
        float py = (float)(ho + kh - 1) + acc[2 * k];
        float px = (float)(wo + kw - 1) + acc[2 * k + 1];
        float m = 1.f / (1.f + __expf(-acc[18 + k]));

        float y0f = floorf(py), x0f = floorf(px);
        float wy1 = py - y0f, wx1 = px - x0f;
        float wy0 = 1.f - wy1, wx0 = 1.f - wx1;
        int y0 = (int)y0f, x0i = (int)x0f;
        int y1 = y0 + 1, x1 = x0i + 1;
        bool vy0 = (unsigned)y0  < (unsigned)HH;
        bool vy1 = (unsigned)y1  < (unsigned)HH;
        bool vx0 = (unsigned)x0i < (unsigned)WW;
        bool vx1 = (unsigned)x1  < (unsigned)WW;
        int cy0 = min(max(y0, 0), HH - 1), cy1 = min(max(y1, 0), HH - 1);
        int cx0 = min(max(x0i, 0), WW - 1), cx1 = min(max(x1, 0), WW - 1);

        float w00 = (vy0 && vx0) ? wy0 * wx0 * m : 0.f;
        float w01 = (vy0 && vx1) ? wy0 * wx1 * m : 0.f;
        float w10 = (vy1 && vx0) ? wy1 * wx0 * m : 0.f;
        float w11 = (vy1 && vx1) ? wy1 * wx1 * m : 0.f;

        g_mw[(size_t)k * BSS + pix] = make_float4(w00, w01, w10, w11);
        g_mi[(size_t)k * BSS + pix] = make_int4(cy0 * WW + cx0, cy0 * WW + cx1,
                                                cy1 * WW + cx0, cy1 * WW + cx1);
    }
}

// ---------------- kernel 2: deformable gather + fp16 mma GEMM ----------------
// CTA: 64 px x 256 oc, 256 threads, 8 warps (2M x 4N), warp 32x64, 2 CTAs/SM.
// K = 18 chunks of 64 ch; A double-buffered (2x8KB), B double-buffered (2x32KB).
// ONE barrier per chunk; 64 MMAs between barriers.
#define DSM_MW   0          // float4[9*64]
#define DSM_MI   9216       // int4[9*64]
#define DSM_A    18432      // 2 x 8192
#define DSM_B    34816      // 2 x 32768
#define DSM_EP   34816      // epilogue staging reuses B
#define DSM_TOT  100352

__global__ __launch_bounds__(256, 2) void deform_mma_kernel(
    float* __restrict__ out, const float* __restrict__ bias)
{
    extern __shared__ char smem[];
    uint32_t sb = smem_u32(smem);
    int tid = threadIdx.x;
    int wid = tid >> 5;
    int lane = tid & 31;

    int tile = blockIdx.x;
    int b = tile / (SS / 64);
    int s0 = (tile - b * (SS / 64)) * 64;

    float4* s_mw4 = (float4*)(smem + DSM_MW);
    int4*   s_mi4 = (int4*)(smem + DSM_MI);

    // load ALL 9 taps' meta for this 64-px tile (one-time)
    for (int i = tid; i < 576; i += 256) {
        size_t mo = (size_t)(i >> 6) * BSS + (size_t)b * SS + s0 + (i & 63);
        s_mw4[i] = g_mw[mo];
        s_mi4[i] = g_mi[mo];
    }

    // prefetch B chunk 0 (32KB)
    {
        const char* gw = (const char*)g_wh;
        uint32_t dst = sb + DSM_B;
        #pragma unroll
        for (int i = 0; i < 8; i++) {
            uint32_t off = (uint32_t)(tid + i * 256) * 16u;
            cp16(dst + off, gw + off);
        }
        asm volatile("cp.async.commit_group;" ::: "memory");
    }
    __syncthreads();   // meta visible to all

    // warp geometry: 2 M-halves (32 px) x 4 N-quarters (64 oc)
    int wm = wid & 1;
    int wn = wid >> 1;
    uint32_t rsel = lane & 15;
    uint32_t csel = (uint32_t)(lane >> 4) * 16u;
    uint32_t xorv = (rsel & 7) * 16u;
    uint32_t aLin = (uint32_t)(wm * 32 + rsel) * 128u + csel;
    uint32_t bLin = (uint32_t)(wn * 64 + rsel) * 128u + csel;

    float acc[64];
    #pragma unroll
    for (int i = 0; i < 64; i++) acc[i] = 0.f;

    int g = tid >> 3, j = tid & 7;     // g: px group (2 px), j: 8-ch group
    const float* xb = g_xt + (size_t)b * SS * CC;

    for (int ch = 0; ch < NCH; ch++) {
        int tap = ch >> 1;
        int c0 = (ch & 1) * 64;

        // ---- gather A chunk: 64 px x 64 ch -> fp16, 128B-row SW128 ----
        {
            uint32_t aw = sb + DSM_A + (uint32_t)(ch & 1) * 8192u;
            const float* xc = xb + c0 + j * 8;
            #pragma unroll
            for (int it = 0; it < 2; it++) {
                int p = g + it * 32;
                float4 wv = s_mw4[tap * 64 + p];
                int4  iv = s_mi4[tap * 64 + p];
                const float* r0 = xc + (size_t)iv.x * CC;
                const float* r1 = xc + (size_t)iv.y * CC;
                const float* r2 = xc + (size_t)iv.z * CC;
                const float* r3 = xc + (size_t)iv.w * CC;
                float4 a0 = *(const float4*)(r0),     a1 = *(const float4*)(r0 + 4);
                float4 b0 = *(const float4*)(r1),     b1 = *(const float4*)(r1 + 4);
                float4 c0v = *(const float4*)(r2),    c1 = *(const float4*)(r2 + 4);
                float4 d0 = *(const float4*)(r3),     d1 = *(const float4*)(r3 + 4);
                float s0v = wv.x*a0.x + wv.y*b0.x + wv.z*c0v.x + wv.w*d0.x;
                float s1v = wv.x*a0.y + wv.y*b0.y + wv.z*c0v.y + wv.w*d0.y;
                float s2v = wv.x*a0.z + wv.y*b0.z + wv.z*c0v.z + wv.w*d0.z;
                float s3v = wv.x*a0.w + wv.y*b0.w + wv.z*c0v.w + wv.w*d0.w;
                float s4v = wv.x*a1.x + wv.y*b1.x + wv.z*c1.x + wv.w*d1.x;
                float s5v = wv.x*a1.y + wv.y*b1.y + wv.z*c1.y + wv.w*d1.y;
                float s6v = wv.x*a1.z + wv.y*b1.z + wv.z*c1.z + wv.w*d1.z;
                float s7v = wv.x*a1.w + wv.y*b1.w + wv.z*c1.w + wv.w*d1.w;
                uint32_t h0 = pkh2(s0v, s1v);
                uint32_t h1 = pkh2(s2v, s3v);
                uint32_t h2 = pkh2(s4v, s5v);
                uint32_t h3 = pkh2(s6v, s7v);
                uint32_t addr = (aw + (uint32_t)p * 128u + (uint32_t)j * 16u)
                                ^ ((uint32_t)(p & 7) << 4);
                asm volatile("st.shared.v4.b32 [%0], {%1,%2,%3,%4};"
                             :: "r"(addr), "r"(h0), "r"(h1), "r"(h2), "r"(h3));
            }
        }

        // B(ch) must be resident before MMA
        asm volatile("cp.async.wait_group 0;" ::: "memory");
        __syncthreads();   // the ONLY barrier per chunk

        // prefetch B(ch+1) (safe: all warps past barrier => MMA(ch-1) done)
        if (ch + 1 < NCH) {
            const char* gw = (const char*)g_wh + (size_t)(ch + 1) * 32768;
            uint32_t dst = sb + DSM_B + (uint32_t)((ch + 1) & 1) * 32768u;
            #pragma unroll
            for (int i = 0; i < 8; i++) {
                uint32_t off = (uint32_t)(tid + i * 256) * 16u;
                cp16(dst + off, gw + off);
            }
            asm volatile("cp.async.commit_group;" ::: "memory");
        }

        // ---- MMA: 4 ksteps x (2 m-tiles x 4 n-groups) ----
        {
            uint32_t aT = sb + DSM_A + (uint32_t)(ch & 1) * 8192u;
            uint32_t bT = sb + DSM_B + (uint32_t)(ch & 1) * 32768u;
            #pragma unroll
            for (int t = 0; t < 4; t++) {
                uint32_t aF[2][4], bF[4][4];
                #pragma unroll
                for (int mt = 0; mt < 2; mt++)
                    ldsm4(aF[mt], (aT + aLin + (uint32_t)mt * 2048u + (uint32_t)t * 32u) ^ xorv);
                #pragma unroll
                for (int ng = 0; ng < 4; ng++)
                    ldsm4(bF[ng], (bT + bLin + (uint32_t)ng * 2048u + (uint32_t)t * 32u) ^ xorv);
                #pragma unroll
                for (int mt = 0; mt < 2; mt++) {
                    #pragma unroll
                    for (int ng = 0; ng < 4; ng++) {
                        mma16816h(&acc[(mt * 8 + ng * 2) * 4],     aF[mt], bF[ng][0], bF[ng][2]);
                        mma16816h(&acc[(mt * 8 + ng * 2 + 1) * 4], aF[mt], bF[ng][1], bF[ng][3]);
                    }
                }
            }
        }
    }
    __syncthreads();

    // ---- epilogue: stage 64-oc quarters in smem, coalesced store ----
    float* sEp = (float*)(smem + DSM_EP);
    int r0l = lane >> 2, c0l = (lane & 3) * 2;
    for (int q = 0; q < 4; q++) {
        if (wn == q) {
            #pragma unroll
            for (int mt = 0; mt < 2; mt++) {
                int px = wm * 32 + mt * 16 + r0l;
                #pragma unroll
                for (int nn = 0; nn < 8; nn++) {
                    float* a4 = &acc[(mt * 8 + nn) * 4];
                    int ocl = nn * 8 + c0l;
                    sEp[ocl * 68 + px]           = a4[0];
                    sEp[(ocl + 1) * 68 + px]     = a4[1];
                    sEp[ocl * 68 + px + 8]       = a4[2];
                    sEp[(ocl + 1) * 68 + px + 8] = a4[3];
                }
            }
        }
        __syncthreads();
        for (int i = tid; i < 1024; i += 256) {
            int r = i >> 4, c = i & 15;
            float4 v = *(float4*)(sEp + r * 68 + c * 4);
            float bv = __ldg(bias + q * 64 + r);
            v.x += bv; v.y += bv; v.z += bv; v.w += bv;
            *(float4*)(out + ((size_t)b * OO + q * 64 + r) * SS + s0 + c * 4) = v;
        }
        __syncthreads();
    }
}

// ---------------- launch ----------------
extern "C" void kernel_launch(void* const* d_in, const int* in_sizes, int n_in,
                              void* d_out, int out_size) {
    const float* x    = (const float*)d_in[0];
    const float* ow   = (const float*)d_in[1];
    const float* ob   = (const float*)d_in[2];
    const float* mw   = (const float*)d_in[3];
    const float* mb   = (const float*)d_in[4];
    const float* w    = (const float*)d_in[5];
    const float* bias = (const float*)d_in[6];
    float* out = (float*)d_out;

    wprep_kernel<<<dim3(OO, NCH), 64>>>(w);
    offmask_kernel<<<dim3(WW / 16, HH / 16, BB), dim3(16, 16)>>>(x, ow, ob, mw, mb);

    cudaFuncSetAttribute(deform_mma_kernel,
                         cudaFuncAttributeMaxDynamicSharedMemorySize, DSM_TOT);
    deform_mma_kernel<<<BSS / 64, 256, DSM_TOT>>>(out, bias);
}

// round 10
// speedup vs baseline: 4.5865x; 1.5584x over previous
#include <cuda_runtime.h>
#include <cuda_bf16.h>
#include <cuda_fp16.h>
#include <cstdint>

// Problem constants
#define BB 8
#define CC 128
#define OO 256
#define HH 96
#define WW 96
#define SS (HH*WW)          // 9216
#define KK 9                // 3x3 taps
#define CK (CC*KK)          // 1152
#define BSS (BB*SS)         // 73728
#define NCH 18              // K chunks of 64 channels (ch = tap*2 + half)

// ---------------- static device scratch (no allocs allowed) ----------------
__device__ __align__(16) float  g_xt[(size_t)BSS*CC];     // x NHWC fp32 (deform gather)
__device__ __align__(16) __half g_xh[(size_t)BSS*CC];     // x NHWC fp16 (offmask mma)
__device__ __align__(16) float4 g_mw[(size_t)KK*BSS];     // corner weights (tap-major)
__device__ __align__(16) int4   g_mi[(size_t)KK*BSS];     // corner indices (tap-major)
__device__ __align__(16) __half g_wh[(size_t)NCH*OO*64];  // fp16 main weights, swizzled
__device__ __align__(16) __half g_wom[(size_t)NCH*32*64]; // fp16 offset+mask weights, swizzled

// ---------------- helpers ----------------
__device__ __forceinline__ uint32_t smem_u32(const void* p) {
    uint32_t a;
    asm("{ .reg .u64 t; cvta.to.shared.u64 t, %1; cvt.u32.u64 %0, t; }" : "=r"(a) : "l"(p));
    return a;
}
// pack two fp32 -> f16x2 (lo in low half)
__device__ __forceinline__ uint32_t pkh2(float lo, float hi) {
    uint32_t r;
    asm("cvt.rn.f16x2.f32 %0, %1, %2;" : "=r"(r) : "f"(hi), "f"(lo));
    return r;
}
__device__ __forceinline__ void ldsm4(uint32_t* r, uint32_t addr) {
    asm volatile("ldmatrix.sync.aligned.m8n8.x4.shared.b16 {%0,%1,%2,%3}, [%4];"
                 : "=r"(r[0]), "=r"(r[1]), "=r"(r[2]), "=r"(r[3]) : "r"(addr));
}
__device__ __forceinline__ void mma16816h(float* c, const uint32_t* a, uint32_t b0, uint32_t b1) {
    asm volatile(
        "mma.sync.aligned.m16n8k16.row.col.f32.f16.f16.f32 "
        "{%0,%1,%2,%3}, {%4,%5,%6,%7}, {%8,%9}, {%0,%1,%2,%3};"
        : "+f"(c[0]), "+f"(c[1]), "+f"(c[2]), "+f"(c[3])
        : "r"(a[0]), "r"(a[1]), "r"(a[2]), "r"(a[3]), "r"(b0), "r"(b1));
}
__device__ __forceinline__ void cp16(uint32_t dst, const void* src) {
    asm volatile("cp.async.cg.shared.global [%0], [%1], 16;" :: "r"(dst), "l"(src));
}
// 16-byte cp.async with zero-fill when srcsize==0 (address must still be valid)
__device__ __forceinline__ void cp16z(uint32_t dst, const void* src, uint32_t srcsize) {
    asm volatile("cp.async.cg.shared.global [%0], [%1], 16, %2;"
                 :: "r"(dst), "l"(src), "r"(srcsize));
}

// ---------------- kernel 0a: NCHW fp32 -> NHWC fp32 + fp16 ----------------
__global__ void transpose_x_kernel(const float* __restrict__ x) {
    __shared__ float tile[32][33];
    int s0 = blockIdx.x * 32;
    int c0 = blockIdx.y * 32;
    int b  = blockIdx.z;
    int tx = threadIdx.x, ty = threadIdx.y;
    #pragma unroll
    for (int i = 0; i < 4; i++) {
        int c = c0 + ty + i * 8;
        tile[ty + i * 8][tx] = x[((size_t)b * CC + c) * SS + s0 + tx];
    }
    __syncthreads();
    #pragma unroll
    for (int i = 0; i < 4; i++) {
        int s = s0 + ty + i * 8;
        g_xt[((size_t)b * SS + s) * CC + c0 + tx] = tile[tx][ty + i * 8];
    }
    int tid = ty * 32 + tx;
    #pragma unroll
    for (int r = 0; r < 2; r++) {
        int idx = tid + r * 256;           // 0..511 over 32 s x 16 ch-pairs
        int sl = idx >> 4, pr = idx & 15;
        __half2 h = __floats2half2_rn(tile[2 * pr][sl], tile[2 * pr + 1][sl]);
        *(__half2*)(g_xh + ((size_t)b * SS + s0 + sl) * CC + c0 + 2 * pr) = h;
    }
}

// ---------------- kernel 0b: main weight -> fp16 swizzled chunk tiles ----------------
__global__ void wprep_kernel(const float* __restrict__ w) {
    int o  = blockIdx.x;        // 0..255
    int ch = blockIdx.y;        // 0..17
    int j  = threadIdx.x;       // 0..63
    int k  = ch >> 1, c = (ch & 1) * 64 + j;
    float v = w[(size_t)o * CK + (size_t)c * KK + k];
    int off = o * 128 + j * 2;
    int sw = off ^ ((o & 7) << 4);
    *(__half*)((char*)g_wh + (size_t)ch * 32768 + sw) = __float2half_rn(v);
}

// ---------------- kernel 0c: offset+mask weight -> fp16 swizzled tiles ----------------
// rows 0..17 = offset_w, 18..26 = mask_w, 27..31 = zero. Tile [32 rows][64 ch].
__global__ void owprep_kernel(const float* __restrict__ ow, const float* __restrict__ mw) {
    int o  = blockIdx.x;        // 0..31
    int ch = blockIdx.y;        // 0..17
    int j  = threadIdx.x;       // 0..63
    int k  = ch >> 1, c = (ch & 1) * 64 + j;
    float v = 0.f;
    if (o < 18)      v = ow[((size_t)o * CC + c) * KK + k];
    else if (o < 27) v = mw[((size_t)(o - 18) * CC + c) * KK + k];
    int off = o * 128 + j * 2;
    int sw = off ^ ((o & 7) << 4);
    *(__half*)((char*)g_wom + (size_t)ch * 4096 + sw) = __float2half_rn(v);
}

// ---------------- kernel 1: offset+mask conv as fp16 MMA + meta epilogue ----------------
// CTA: 128 px x 32 oc, 256 threads, 8 warps (4M x 2N). A built fully via cp.async im2col.
#define OSM_A    0          // 2 x 16384
#define OSM_B    32768      // 2 x 4096
#define OSM_EP   0          // epilogue staging reuses A
#define OSM_TOT  40960

__global__ __launch_bounds__(256) void offmask_mma_kernel(
    const float* __restrict__ ob, const float* __restrict__ mb)
{
    extern __shared__ char smem[];
    uint32_t sb = smem_u32(smem);
    int tid = threadIdx.x;
    int wid = tid >> 5;
    int lane = tid & 31;

    int tile = blockIdx.x;
    int b = tile / (SS / 128);
    int s0 = (tile - b * (SS / 128)) * 128;

    const __half* xh = g_xh + (size_t)b * SS * CC;

    auto issueA = [&](int ch) {
        int tap = ch >> 1, c0 = (ch & 1) * 64;
        int dy = tap / 3 - 1, dx = tap % 3 - 1;
        uint32_t aw = sb + OSM_A + (uint32_t)(ch & 1) * 16384u;
        #pragma unroll
        for (int r = 0; r < 4; r++) {
            int i = tid + r * 256;          // 0..1023 over 128 px x 8 segs
            int px = i >> 3, seg = i & 7;
            int s = s0 + px;
            int y = s / WW, xq = s - y * WW;
            int sy = y + dy, sx = xq + dx;
            bool vld = ((unsigned)sy < (unsigned)HH) && ((unsigned)sx < (unsigned)WW);
            int syc = min(max(sy, 0), HH - 1), sxc = min(max(sx, 0), WW - 1);
            const char* src = (const char*)(xh + (size_t)(syc * WW + sxc) * CC + c0) + seg * 16;
            uint32_t dst = (aw + (uint32_t)px * 128u + (uint32_t)seg * 16u)
                           ^ ((uint32_t)(px & 7) << 4);
            cp16z(dst, src, vld ? 16u : 0u);
        }
        // B chunk: 4KB
        uint32_t bw = sb + OSM_B + (uint32_t)(ch & 1) * 4096u;
        const char* gb = (const char*)g_wom + (size_t)ch * 4096;
        cp16(bw + (uint32_t)tid * 16u, gb + (size_t)tid * 16);
        asm volatile("cp.async.commit_group;" ::: "memory");
    };

    // warp geometry: 4 M-quarters (32 px) x 2 N-halves (16 oc)
    int wm = wid & 3;
    int wn = wid >> 2;
    uint32_t rsel = lane & 15;
    uint32_t csel = (uint32_t)(lane >> 4) * 16u;
    uint32_t xorv = (rsel & 7) * 16u;
    uint32_t aLin = (uint32_t)(wm * 32 + rsel) * 128u + csel;
    uint32_t bLin = (uint32_t)(wn * 16 + rsel) * 128u + csel;

    float acc[16];
    #pragma unroll
    for (int i = 0; i < 16; i++) acc[i] = 0.f;

    issueA(0);
    for (int ch = 0; ch < NCH; ch++) {
        asm volatile("cp.async.wait_group 0;" ::: "memory");
        __syncthreads();
        if (ch + 1 < NCH) issueA(ch + 1);

        uint32_t aT = sb + OSM_A + (uint32_t)(ch & 1) * 16384u;
        uint32_t bT = sb + OSM_B + (uint32_t)(ch & 1) * 4096u;
        #pragma unroll
        for (int t = 0; t < 4; t++) {
            uint32_t aF[2][4], bF[4];
            #pragma unroll
            for (int mt = 0; mt < 2; mt++)
                ldsm4(aF[mt], (aT + aLin + (uint32_t)mt * 2048u + (uint32_t)t * 32u) ^ xorv);
            ldsm4(bF, (bT + bLin + (uint32_t)t * 32u) ^ xorv);
            mma16816h(&acc[0],  aF[0], bF[0], bF[2]);
            mma16816h(&acc[4],  aF[0], bF[1], bF[3]);
            mma16816h(&acc[8],  aF[1], bF[0], bF[2]);
            mma16816h(&acc[12], aF[1], bF[1], bF[3]);
        }
        __syncthreads();
    }

    // ---- stage accumulators: sEp[px][32 oc] ----
    float* sEp = (float*)(smem + OSM_EP);
    int r0 = lane >> 2, cl = (lane & 3) * 2;
    #pragma unroll
    for (int mt = 0; mt < 2; mt++) {
        #pragma unroll
        for (int n8 = 0; n8 < 2; n8++) {
            float* a4 = &acc[(mt * 2 + n8) * 4];
            int px = wm * 32 + mt * 16 + r0;
            int oc = wn * 16 + n8 * 8 + cl;
            sEp[px * 32 + oc]           = a4[0];
            sEp[px * 32 + oc + 1]       = a4[1];
            sEp[(px + 8) * 32 + oc]     = a4[2];
            sEp[(px + 8) * 32 + oc + 1] = a4[3];
        }
    }
    __syncthreads();

    // ---- meta epilogue: one thread per pixel ----
    if (tid < 128) {
        int s = s0 + tid;
        int y = s / WW, xq = s - y * WW;
        float a[27];
        #pragma unroll
        for (int oc = 0; oc < 18; oc++) a[oc] = sEp[tid * 32 + oc] + ob[oc];
        #pragma unroll
        for (int oc = 18; oc < 27; oc++) a[oc] = sEp[tid * 32 + oc] + mb[oc - 18];

        size_t pix = (size_t)b * SS + s;
        #pragma unroll
        for (int k = 0; k < 9; k++) {
            int kh = k / 3, kw = k % 3;
            float py = (float)(y + kh - 1) + a[2 * k];
            float px_ = (float)(xq + kw - 1) + a[2 * k + 1];
            float m = 1.f / (1.f + __expf(-a[18 + k]));

            float y0f = floorf(py), x0f = floorf(px_);
            float wy1 = py - y0f, wx1 = px_ - x0f;
            float wy0 = 1.f - wy1, wx0 = 1.f - wx1;
            int y0 = (int)y0f, x0i = (int)x0f;
            int y1 = y0 + 1, x1 = x0i + 1;
            bool vy0 = (unsigned)y0  < (unsigned)HH;
            bool vy1 = (unsigned)y1  < (unsigned)HH;
            bool vx0 = (unsigned)x0i < (unsigned)WW;
            bool vx1 = (unsigned)x1  < (unsigned)WW;
            int cy0 = min(max(y0, 0), HH - 1), cy1 = min(max(y1, 0), HH - 1);
            int cx0 = min(max(x0i, 0), WW - 1), cx1 = min(max(x1, 0), WW - 1);

            float w00 = (vy0 && vx0) ? wy0 * wx0 * m : 0.f;
            float w01 = (vy0 && vx1) ? wy0 * wx1 * m : 0.f;
            float w10 = (vy1 && vx0) ? wy1 * wx0 * m : 0.f;
            float w11 = (vy1 && vx1) ? wy1 * wx1 * m : 0.f;

            g_mw[(size_t)k * BSS + pix] = make_float4(w00, w01, w10, w11);
            g_mi[(size_t)k * BSS + pix] = make_int4(cy0 * WW + cx0, cy0 * WW + cx1,
                                                    cy1 * WW + cx0, cy1 * WW + cx1);
        }
    }
}

// ---------------- kernel 2: deformable gather + fp16 mma GEMM ----------------
// CTA: 64 px x 256 oc, 256 threads, 8 warps (2M x 4N), warp 32x64, 2 CTAs/SM.
// K = 18 chunks of 64 ch; A double-buffered (2x8KB), B double-buffered (2x32KB).
#define DSM_MW   0          // float4[9*64]
#define DSM_MI   9216       // int4[9*64]
#define DSM_A    18432      // 2 x 8192
#define DSM_B    34816      // 2 x 32768
#define DSM_EP   34816      // epilogue staging reuses B
#define DSM_TOT  100352

__global__ __launch_bounds__(256, 2) void deform_mma_kernel(
    float* __restrict__ out, const float* __restrict__ bias)
{
    extern __shared__ char smem[];
    uint32_t sb = smem_u32(smem);
    int tid = threadIdx.x;
    int wid = tid >> 5;
    int lane = tid & 31;

    int tile = blockIdx.x;
    int b = tile / (SS / 64);
    int s0 = (tile - b * (SS / 64)) * 64;

    float4* s_mw4 = (float4*)(smem + DSM_MW);
    int4*   s_mi4 = (int4*)(smem + DSM_MI);

    // load ALL 9 taps' meta for this 64-px tile (one-time)
    for (int i = tid; i < 576; i += 256) {
        size_t mo = (size_t)(i >> 6) * BSS + (size_t)b * SS + s0 + (i & 63);
        s_mw4[i] = g_mw[mo];
        s_mi4[i] = g_mi[mo];
    }

    // prefetch B chunk 0 (32KB)
    {
        const char* gw = (const char*)g_wh;
        uint32_t dst = sb + DSM_B;
        #pragma unroll
        for (int i = 0; i < 8; i++) {
            uint32_t off = (uint32_t)(tid + i * 256) * 16u;
            cp16(dst + off, gw + off);
        }
        asm volatile("cp.async.commit_group;" ::: "memory");
    }
    __syncthreads();   // meta visible to all

    // warp geometry: 2 M-halves (32 px) x 4 N-quarters (64 oc)
    int wm = wid & 1;
    int wn = wid >> 1;
    uint32_t rsel = lane & 15;
    uint32_t csel = (uint32_t)(lane >> 4) * 16u;
    uint32_t xorv = (rsel & 7) * 16u;
    uint32_t aLin = (uint32_t)(wm * 32 + rsel) * 128u + csel;
    uint32_t bLin = (uint32_t)(wn * 64 + rsel) * 128u + csel;

    float acc[64];
    #pragma unroll
    for (int i = 0; i < 64; i++) acc[i] = 0.f;

    int g = tid >> 3, j = tid & 7;     // g: px group (2 px), j: 8-ch group
    const float* xb = g_xt + (size_t)b * SS * CC;

    for (int ch = 0; ch < NCH; ch++) {
        int tap = ch >> 1;
        int c0 = (ch & 1) * 64;

        // ---- gather A chunk: 64 px x 64 ch -> fp16, 128B-row SW128 ----
        {
            uint32_t aw = sb + DSM_A + (uint32_t)(ch & 1) * 8192u;
            const float* xc = xb + c0 + j * 8;
            #pragma unroll
            for (int it = 0; it < 2; it++) {
                int p = g + it * 32;
                float4 wv = s_mw4[tap * 64 + p];
                int4  iv = s_mi4[tap * 64 + p];
                const float* r0 = xc + (size_t)iv.x * CC;
                const float* r1 = xc + (size_t)iv.y * CC;
                const float* r2 = xc + (size_t)iv.z * CC;
                const float* r3 = xc + (size_t)iv.w * CC;
                float4 a0 = *(const float4*)(r0),     a1 = *(const float4*)(r0 + 4);
                float4 b0 = *(const float4*)(r1),     b1 = *(const float4*)(r1 + 4);
                float4 c0v = *(const float4*)(r2),    c1 = *(const float4*)(r2 + 4);
                float4 d0 = *(const float4*)(r3),     d1 = *(const float4*)(r3 + 4);
                float s0v = wv.x*a0.x + wv.y*b0.x + wv.z*c0v.x + wv.w*d0.x;
                float s1v = wv.x*a0.y + wv.y*b0.y + wv.z*c0v.y + wv.w*d0.y;
                float s2v = wv.x*a0.z + wv.y*b0.z + wv.z*c0v.z + wv.w*d0.z;
                float s3v = wv.x*a0.w + wv.y*b0.w + wv.z*c0v.w + wv.w*d0.w;
                float s4v = wv.x*a1.x + wv.y*b1.x + wv.z*c1.x + wv.w*d1.x;
                float s5v = wv.x*a1.y + wv.y*b1.y + wv.z*c1.y + wv.w*d1.y;
                float s6v = wv.x*a1.z + wv.y*b1.z + wv.z*c1.z + wv.w*d1.z;
                float s7v = wv.x*a1.w + wv.y*b1.w + wv.z*c1.w + wv.w*d1.w;
                uint32_t h0 = pkh2(s0v, s1v);
                uint32_t h1 = pkh2(s2v, s3v);
                uint32_t h2 = pkh2(s4v, s5v);
                uint32_t h3 = pkh2(s6v, s7v);
                uint32_t addr = (aw + (uint32_t)p * 128u + (uint32_t)j * 16u)
                                ^ ((uint32_t)(p & 7) << 4);
                asm volatile("st.shared.v4.b32 [%0], {%1,%2,%3,%4};"
                             :: "r"(addr), "r"(h0), "r"(h1), "r"(h2), "r"(h3));
            }
        }

        // B(ch) must be resident before MMA
        asm volatile("cp.async.wait_group 0;" ::: "memory");
        __syncthreads();   // the ONLY barrier per chunk

        // prefetch B(ch+1) (safe: all warps past barrier => MMA(ch-1) done)
        if (ch + 1 < NCH) {
            const char* gw = (const char*)g_wh + (size_t)(ch + 1) * 32768;
            uint32_t dst = sb + DSM_B + (uint32_t)((ch + 1) & 1) * 32768u;
            #pragma unroll
            for (int i = 0; i < 8; i++) {
                uint32_t off = (uint32_t)(tid + i * 256) * 16u;
                cp16(dst + off, gw + off);
            }
            asm volatile("cp.async.commit_group;" ::: "memory");
        }

        // ---- MMA: 4 ksteps x (2 m-tiles x 4 n-groups) ----
        {
            uint32_t aT = sb + DSM_A + (uint32_t)(ch & 1) * 8192u;
            uint32_t bT = sb + DSM_B + (uint32_t)(ch & 1) * 32768u;
            #pragma unroll
            for (int t = 0; t < 4; t++) {
                uint32_t aF[2][4], bF[4][4];
                #pragma unroll
                for (int mt = 0; mt < 2; mt++)
                    ldsm4(aF[mt], (aT + aLin + (uint32_t)mt * 2048u + (uint32_t)t * 32u) ^ xorv);
                #pragma unroll
                for (int ng = 0; ng < 4; ng++)
                    ldsm4(bF[ng], (bT + bLin + (uint32_t)ng * 2048u + (uint32_t)t * 32u) ^ xorv);
                #pragma unroll
                for (int mt = 0; mt < 2; mt++) {
                    #pragma unroll
                    for (int ng = 0; ng < 4; ng++) {
                        mma16816h(&acc[(mt * 8 + ng * 2) * 4],     aF[mt], bF[ng][0], bF[ng][2]);
                        mma16816h(&acc[(mt * 8 + ng * 2 + 1) * 4], aF[mt], bF[ng][1], bF[ng][3]);
                    }
                }
            }
        }
    }
    __syncthreads();

    // ---- epilogue: stage 64-oc quarters in smem, coalesced store ----
    float* sEp = (float*)(smem + DSM_EP);
    int r0l = lane >> 2, c0l = (lane & 3) * 2;
    for (int q = 0; q < 4; q++) {
        if (wn == q) {
            #pragma unroll
            for (int mt = 0; mt < 2; mt++) {
                int px = wm * 32 + mt * 16 + r0l;
                #pragma unroll
                for (int nn = 0; nn < 8; nn++) {
                    float* a4 = &acc[(mt * 8 + nn) * 4];
                    int ocl = nn * 8 + c0l;
                    sEp[ocl * 68 + px]           = a4[0];
                    sEp[(ocl + 1) * 68 + px]     = a4[1];
                    sEp[ocl * 68 + px + 8]       = a4[2];
                    sEp[(ocl + 1) * 68 + px + 8] = a4[3];
                }
            }
        }
        __syncthreads();
        for (int i = tid; i < 1024; i += 256) {
            int r = i >> 4, c = i & 15;
            float4 v = *(float4*)(sEp + r * 68 + c * 4);
            float bv = __ldg(bias + q * 64 + r);
            v.x += bv; v.y += bv; v.z += bv; v.w += bv;
            *(float4*)(out + ((size_t)b * OO + q * 64 + r) * SS + s0 + c * 4) = v;
        }
        __syncthreads();
    }
}

// ---------------- launch ----------------
extern "C" void kernel_launch(void* const* d_in, const int* in_sizes, int n_in,
                              void* d_out, int out_size) {
    const float* x    = (const float*)d_in[0];
    const float* ow   = (const float*)d_in[1];
    const float* ob   = (const float*)d_in[2];
    const float* mw   = (const float*)d_in[3];
    const float* mb   = (const float*)d_in[4];
    const float* w    = (const float*)d_in[5];
    const float* bias = (const float*)d_in[6];
    float* out = (float*)d_out;

    transpose_x_kernel<<<dim3(SS / 32, CC / 32, BB), dim3(32, 8)>>>(x);
    wprep_kernel<<<dim3(OO, NCH), 64>>>(w);
    owprep_kernel<<<dim3(32, NCH), 64>>>(ow, mw);

    cudaFuncSetAttribute(offmask_mma_kernel,
                         cudaFuncAttributeMaxDynamicSharedMemorySize, OSM_TOT);
    offmask_mma_kernel<<<BSS / 128, 256, OSM_TOT>>>(ob, mb);

    cudaFuncSetAttribute(deform_mma_kernel,
                         cudaFuncAttributeMaxDynamicSharedMemorySize, DSM_TOT);
    deform_mma_kernel<<<BSS / 64, 256, DSM_TOT>>>(out, bias);
}

// round 11
// speedup vs baseline: 5.0824x; 1.1081x over previous
#include <cuda_runtime.h>
#include <cuda_bf16.h>
#include <cuda_fp16.h>
#include <cstdint>

// Problem constants
#define BB 8
#define CC 128
#define OO 256
#define HH 96
#define WW 96
#define SS (HH*WW)          // 9216
#define KK 9                // 3x3 taps
#define CK (CC*KK)          // 1152
#define BSS (BB*SS)         // 73728
#define NCH 18              // K chunks of 64 channels (ch = tap*2 + half)

// ---------------- static device scratch (no allocs allowed) ----------------
__device__ __align__(16) __half g_xh[(size_t)BSS*CC];     // x NHWC fp16 (both gathers)
__device__ __align__(16) float4 g_mw[(size_t)KK*BSS];     // corner weights (tap-major)
__device__ __align__(16) int4   g_mi[(size_t)KK*BSS];     // corner indices (tap-major)
__device__ __align__(16) __half g_wh[(size_t)NCH*OO*64];  // fp16 main weights, swizzled
__device__ __align__(16) __half g_wom[(size_t)NCH*32*64]; // fp16 offset+mask weights, swizzled

// ---------------- helpers ----------------
__device__ __forceinline__ uint32_t smem_u32(const void* p) {
    uint32_t a;
    asm("{ .reg .u64 t; cvta.to.shared.u64 t, %1; cvt.u32.u64 %0, t; }" : "=r"(a) : "l"(p));
    return a;
}
// pack two fp32 -> f16x2 (lo in low half)
__device__ __forceinline__ uint32_t pkh2(float lo, float hi) {
    uint32_t r;
    asm("cvt.rn.f16x2.f32 %0, %1, %2;" : "=r"(r) : "f"(hi), "f"(lo));
    return r;
}
__device__ __forceinline__ void ldsm4(uint32_t* r, uint32_t addr) {
    asm volatile("ldmatrix.sync.aligned.m8n8.x4.shared.b16 {%0,%1,%2,%3}, [%4];"
                 : "=r"(r[0]), "=r"(r[1]), "=r"(r[2]), "=r"(r[3]) : "r"(addr));
}
__device__ __forceinline__ void mma16816h(float* c, const uint32_t* a, uint32_t b0, uint32_t b1) {
    asm volatile(
        "mma.sync.aligned.m16n8k16.row.col.f32.f16.f16.f32 "
        "{%0,%1,%2,%3}, {%4,%5,%6,%7}, {%8,%9}, {%0,%1,%2,%3};"
        : "+f"(c[0]), "+f"(c[1]), "+f"(c[2]), "+f"(c[3])
        : "r"(a[0]), "r"(a[1]), "r"(a[2]), "r"(a[3]), "r"(b0), "r"(b1));
}
__device__ __forceinline__ void cp16(uint32_t dst, const void* src) {
    asm volatile("cp.async.cg.shared.global [%0], [%1], 16;" :: "r"(dst), "l"(src));
}
// 16-byte cp.async with zero-fill when srcsize==0 (address must still be valid)
__device__ __forceinline__ void cp16z(uint32_t dst, const void* src, uint32_t srcsize) {
    asm volatile("cp.async.cg.shared.global [%0], [%1], 16, %2;"
                 :: "r"(dst), "l"(src), "r"(srcsize));
}

// ---------------- kernel 0a: NCHW fp32 -> NHWC fp16 ----------------
__global__ void transpose_x_kernel(const float* __restrict__ x) {
    __shared__ float tile[32][33];
    int s0 = blockIdx.x * 32;
    int c0 = blockIdx.y * 32;
    int b  = blockIdx.z;
    int tx = threadIdx.x, ty = threadIdx.y;
    #pragma unroll
    for (int i = 0; i < 4; i++) {
        int c = c0 + ty + i * 8;
        tile[ty + i * 8][tx] = x[((size_t)b * CC + c) * SS + s0 + tx];
    }
    __syncthreads();
    int tid = ty * 32 + tx;
    #pragma unroll
    for (int r = 0; r < 2; r++) {
        int idx = tid + r * 256;           // 0..511 over 32 s x 16 ch-pairs
        int sl = idx >> 4, pr = idx & 15;
        __half2 h = __floats2half2_rn(tile[2 * pr][sl], tile[2 * pr + 1][sl]);
        *(__half2*)(g_xh + ((size_t)b * SS + s0 + sl) * CC + c0 + 2 * pr) = h;
    }
}

// ---------------- kernel 0b: main weight -> fp16 swizzled chunk tiles ----------------
__global__ void wprep_kernel(const float* __restrict__ w) {
    int o  = blockIdx.x;        // 0..255
    int ch = blockIdx.y;        // 0..17
    int j  = threadIdx.x;       // 0..63
    int k  = ch >> 1, c = (ch & 1) * 64 + j;
    float v = w[(size_t)o * CK + (size_t)c * KK + k];
    int off = o * 128 + j * 2;
    int sw = off ^ ((o & 7) << 4);
    *(__half*)((char*)g_wh + (size_t)ch * 32768 + sw) = __float2half_rn(v);
}

// ---------------- kernel 0c: offset+mask weight -> fp16 swizzled tiles ----------------
// rows 0..17 = offset_w, 18..26 = mask_w, 27..31 = zero. Tile [32 rows][64 ch].
__global__ void owprep_kernel(const float* __restrict__ ow, const float* __restrict__ mw) {
    int o  = blockIdx.x;        // 0..31
    int ch = blockIdx.y;        // 0..17
    int j  = threadIdx.x;       // 0..63
    int k  = ch >> 1, c = (ch & 1) * 64 + j;
    float v = 0.f;
    if (o < 18)      v = ow[((size_t)o * CC + c) * KK + k];
    else if (o < 27) v = mw[((size_t)(o - 18) * CC + c) * KK + k];
    int off = o * 128 + j * 2;
    int sw = off ^ ((o & 7) << 4);
    *(__half*)((char*)g_wom + (size_t)ch * 4096 + sw) = __float2half_rn(v);
}

// ---------------- kernel 1: offset+mask conv as fp16 MMA + meta epilogue ----------------
// CTA: 128 px x 32 oc, 256 threads, 8 warps (4M x 2N). A built fully via cp.async im2col.
#define OSM_A    0          // 2 x 16384
#define OSM_B    32768      // 2 x 4096
#define OSM_EP   0          // epilogue staging reuses A
#define OSM_TOT  40960

__global__ __launch_bounds__(256) void offmask_mma_kernel(
    const float* __restrict__ ob, const float* __restrict__ mb)
{
    extern __shared__ char smem[];
    uint32_t sb = smem_u32(smem);
    int tid = threadIdx.x;
    int wid = tid >> 5;
    int lane = tid & 31;

    int tile = blockIdx.x;
    int b = tile / (SS / 128);
    int s0 = (tile - b * (SS / 128)) * 128;

    const __half* xh = g_xh + (size_t)b * SS * CC;

    auto issueA = [&](int ch) {
        int tap = ch >> 1, c0 = (ch & 1) * 64;
        int dy = tap / 3 - 1, dx = tap % 3 - 1;
        uint32_t aw = sb + OSM_A + (uint32_t)(ch & 1) * 16384u;
        #pragma unroll
        for (int r = 0; r < 4; r++) {
            int i = tid + r * 256;          // 0..1023 over 128 px x 8 segs
            int px = i >> 3, seg = i & 7;
            int s = s0 + px;
            int y = s / WW, xq = s - y * WW;
            int sy = y + dy, sx = xq + dx;
            bool vld = ((unsigned)sy < (unsigned)HH) && ((unsigned)sx < (unsigned)WW);
            int syc = min(max(sy, 0), HH - 1), sxc = min(max(sx, 0), WW - 1);
            const char* src = (const char*)(xh + (size_t)(syc * WW + sxc) * CC + c0) + seg * 16;
            uint32_t dst = (aw + (uint32_t)px * 128u + (uint32_t)seg * 16u)
                           ^ ((uint32_t)(px & 7) << 4);
            cp16z(dst, src, vld ? 16u : 0u);
        }
        // B chunk: 4KB
        uint32_t bw = sb + OSM_B + (uint32_t)(ch & 1) * 4096u;
        const char* gb = (const char*)g_wom + (size_t)ch * 4096;
        cp16(bw + (uint32_t)tid * 16u, gb + (size_t)tid * 16);
        asm volatile("cp.async.commit_group;" ::: "memory");
    };

    // warp geometry: 4 M-quarters (32 px) x 2 N-halves (16 oc)
    int wm = wid & 3;
    int wn = wid >> 2;
    uint32_t rsel = lane & 15;
    uint32_t csel = (uint32_t)(lane >> 4) * 16u;
    uint32_t xorv = (rsel & 7) * 16u;
    uint32_t aLin = (uint32_t)(wm * 32 + rsel) * 128u + csel;
    uint32_t bLin = (uint32_t)(wn * 16 + rsel) * 128u + csel;

    float acc[16];
    #pragma unroll
    for (int i = 0; i < 16; i++) acc[i] = 0.f;

    issueA(0);
    for (int ch = 0; ch < NCH; ch++) {
        asm volatile("cp.async.wait_group 0;" ::: "memory");
        __syncthreads();
        if (ch + 1 < NCH) issueA(ch + 1);

        uint32_t aT = sb + OSM_A + (uint32_t)(ch & 1) * 16384u;
        uint32_t bT = sb + OSM_B + (uint32_t)(ch & 1) * 4096u;
        #pragma unroll
        for (int t = 0; t < 4; t++) {
            uint32_t aF[2][4], bF[4];
            #pragma unroll
            for (int mt = 0; mt < 2; mt++)
                ldsm4(aF[mt], (aT + aLin + (uint32_t)mt * 2048u + (uint32_t)t * 32u) ^ xorv);
            ldsm4(bF, (bT + bLin + (uint32_t)t * 32u) ^ xorv);
            mma16816h(&acc[0],  aF[0], bF[0], bF[2]);
            mma16816h(&acc[4],  aF[0], bF[1], bF[3]);
            mma16816h(&acc[8],  aF[1], bF[0], bF[2]);
            mma16816h(&acc[12], aF[1], bF[1], bF[3]);
        }
        __syncthreads();
    }

    // ---- stage accumulators: sEp[px][32 oc] ----
    float* sEp = (float*)(smem + OSM_EP);
    int r0 = lane >> 2, cl = (lane & 3) * 2;
    #pragma unroll
    for (int mt = 0; mt < 2; mt++) {
        #pragma unroll
        for (int n8 = 0; n8 < 2; n8++) {
            float* a4 = &acc[(mt * 2 + n8) * 4];
            int px = wm * 32 + mt * 16 + r0;
            int oc = wn * 16 + n8 * 8 + cl;
            sEp[px * 32 + oc]           = a4[0];
            sEp[px * 32 + oc + 1]       = a4[1];
            sEp[(px + 8) * 32 + oc]     = a4[2];
            sEp[(px + 8) * 32 + oc + 1] = a4[3];
        }
    }
    __syncthreads();

    // ---- meta epilogue: one thread per pixel ----
    if (tid < 128) {
        int s = s0 + tid;
        int y = s / WW, xq = s - y * WW;
        float a[27];
        #pragma unroll
        for (int oc = 0; oc < 18; oc++) a[oc] = sEp[tid * 32 + oc] + ob[oc];
        #pragma unroll
        for (int oc = 18; oc < 27; oc++) a[oc] = sEp[tid * 32 + oc] + mb[oc - 18];

        size_t pix = (size_t)b * SS + s;
        #pragma unroll
        for (int k = 0; k < 9; k++) {
            int kh = k / 3, kw = k % 3;
            float py = (float)(y + kh - 1) + a[2 * k];
            float px_ = (float)(xq + kw - 1) + a[2 * k + 1];
            float m = 1.f / (1.f + __expf(-a[18 + k]));

            float y0f = floorf(py), x0f = floorf(px_);
            float wy1 = py - y0f, wx1 = px_ - x0f;
            float wy0 = 1.f - wy1, wx0 = 1.f - wx1;
            int y0 = (int)y0f, x0i = (int)x0f;
            int y1 = y0 + 1, x1 = x0i + 1;
            bool vy0 = (unsigned)y0  < (unsigned)HH;
            bool vy1 = (unsigned)y1  < (unsigned)HH;
            bool vx0 = (unsigned)x0i < (unsigned)WW;
            bool vx1 = (unsigned)x1  < (unsigned)WW;
            int cy0 = min(max(y0, 0), HH - 1), cy1 = min(max(y1, 0), HH - 1);
            int cx0 = min(max(x0i, 0), WW - 1), cx1 = min(max(x1, 0), WW - 1);

            float w00 = (vy0 && vx0) ? wy0 * wx0 * m : 0.f;
            float w01 = (vy0 && vx1) ? wy0 * wx1 * m : 0.f;
            float w10 = (vy1 && vx0) ? wy1 * wx0 * m : 0.f;
            float w11 = (vy1 && vx1) ? wy1 * wx1 * m : 0.f;

            g_mw[(size_t)k * BSS + pix] = make_float4(w00, w01, w10, w11);
            g_mi[(size_t)k * BSS + pix] = make_int4(cy0 * WW + cx0, cy0 * WW + cx1,
                                                    cy1 * WW + cx0, cy1 * WW + cx1);
        }
    }
}

// ---------------- kernel 2: deformable gather (fp16 src) + fp16 mma GEMM ----------------
// CTA: 64 px x 256 oc, 256 threads, 8 warps (2M x 4N), warp 32x64, 2 CTAs/SM.
// K = 18 chunks of 64 ch; A double-buffered (2x8KB), B double-buffered (2x32KB).
#define DSM_MW   0          // float4[9*64]
#define DSM_MI   9216       // int4[9*64]
#define DSM_A    18432      // 2 x 8192
#define DSM_B    34816      // 2 x 32768
#define DSM_EP   34816      // epilogue staging reuses B
#define DSM_TOT  100352

__global__ __launch_bounds__(256, 2) void deform_mma_kernel(
    float* __restrict__ out, const float* __restrict__ bias)
{
    extern __shared__ char smem[];
    uint32_t sb = smem_u32(smem);
    int tid = threadIdx.x;
    int wid = tid >> 5;
    int lane = tid & 31;

    int tile = blockIdx.x;
    int b = tile / (SS / 64);
    int s0 = (tile - b * (SS / 64)) * 64;

    float4* s_mw4 = (float4*)(smem + DSM_MW);
    int4*   s_mi4 = (int4*)(smem + DSM_MI);

    // load ALL 9 taps' meta for this 64-px tile (one-time)
    for (int i = tid; i < 576; i += 256) {
        size_t mo = (size_t)(i >> 6) * BSS + (size_t)b * SS + s0 + (i & 63);
        s_mw4[i] = g_mw[mo];
        s_mi4[i] = g_mi[mo];
    }

    // prefetch B chunk 0 (32KB)
    {
        const char* gw = (const char*)g_wh;
        uint32_t dst = sb + DSM_B;
        #pragma unroll
        for (int i = 0; i < 8; i++) {
            uint32_t off = (uint32_t)(tid + i * 256) * 16u;
            cp16(dst + off, gw + off);
        }
        asm volatile("cp.async.commit_group;" ::: "memory");
    }
    __syncthreads();   // meta visible to all

    // warp geometry: 2 M-halves (32 px) x 4 N-quarters (64 oc)
    int wm = wid & 1;
    int wn = wid >> 1;
    uint32_t rsel = lane & 15;
    uint32_t csel = (uint32_t)(lane >> 4) * 16u;
    uint32_t xorv = (rsel & 7) * 16u;
    uint32_t aLin = (uint32_t)(wm * 32 + rsel) * 128u + csel;
    uint32_t bLin = (uint32_t)(wn * 64 + rsel) * 128u + csel;

    float acc[64];
    #pragma unroll
    for (int i = 0; i < 64; i++) acc[i] = 0.f;

    int g = tid >> 3, j = tid & 7;     // g: px group (2 px), j: 8-ch group
    const __half* xb = g_xh + (size_t)b * SS * CC;

    for (int ch = 0; ch < NCH; ch++) {
        int tap = ch >> 1;
        int c0 = (ch & 1) * 64;

        // ---- gather A chunk: 64 px x 64 ch (fp16 src) -> fp16, 128B-row SW128 ----
        {
            uint32_t aw = sb + DSM_A + (uint32_t)(ch & 1) * 8192u;
            const __half* xc = xb + c0 + j * 8;
            #pragma unroll
            for (int it = 0; it < 2; it++) {
                int p = g + it * 32;
                float4 wv = s_mw4[tap * 64 + p];
                int4  iv = s_mi4[tap * 64 + p];
                uint4 ra = *(const uint4*)(xc + (size_t)iv.x * CC);
                uint4 rb = *(const uint4*)(xc + (size_t)iv.y * CC);
                uint4 rc = *(const uint4*)(xc + (size_t)iv.z * CC);
                uint4 rd = *(const uint4*)(xc + (size_t)iv.w * CC);
                uint32_t va[4] = {ra.x, ra.y, ra.z, ra.w};
                uint32_t vb[4] = {rb.x, rb.y, rb.z, rb.w};
                uint32_t vc[4] = {rc.x, rc.y, rc.z, rc.w};
                uint32_t vd[4] = {rd.x, rd.y, rd.z, rd.w};
                uint32_t hres[4];
                #pragma unroll
                for (int q = 0; q < 4; q++) {
                    float2 fa = __half22float2(*reinterpret_cast<__half2*>(&va[q]));
                    float2 fb = __half22float2(*reinterpret_cast<__half2*>(&vb[q]));
                    float2 fc = __half22float2(*reinterpret_cast<__half2*>(&vc[q]));
                    float2 fd = __half22float2(*reinterpret_cast<__half2*>(&vd[q]));
                    float sx = wv.x * fa.x + wv.y * fb.x + wv.z * fc.x + wv.w * fd.x;
                    float sy = wv.x * fa.y + wv.y * fb.y + wv.z * fc.y + wv.w * fd.y;
                    hres[q] = pkh2(sx, sy);
                }
                uint32_t addr = (aw + (uint32_t)p * 128u + (uint32_t)j * 16u)
                                ^ ((uint32_t)(p & 7) << 4);
                asm volatile("st.shared.v4.b32 [%0], {%1,%2,%3,%4};"
                             :: "r"(addr), "r"(hres[0]), "r"(hres[1]),
                                "r"(hres[2]), "r"(hres[3]));
            }
        }

        // B(ch) must be resident before MMA
        asm volatile("cp.async.wait_group 0;" ::: "memory");
        __syncthreads();   // the ONLY barrier per chunk

        // prefetch B(ch+1) (safe: all warps past barrier => MMA(ch-1) done)
        if (ch + 1 < NCH) {
            const char* gw = (const char*)g_wh + (size_t)(ch + 1) * 32768;
            uint32_t dst = sb + DSM_B + (uint32_t)((ch + 1) & 1) * 32768u;
            #pragma unroll
            for (int i = 0; i < 8; i++) {
                uint32_t off = (uint32_t)(tid + i * 256) * 16u;
                cp16(dst + off, gw + off);
            }
            asm volatile("cp.async.commit_group;" ::: "memory");
        }

        // ---- MMA: 4 ksteps x (2 m-tiles x 4 n-groups) ----
        {
            uint32_t aT = sb + DSM_A + (uint32_t)(ch & 1) * 8192u;
            uint32_t bT = sb + DSM_B + (uint32_t)(ch & 1) * 32768u;
            #pragma unroll
            for (int t = 0; t < 4; t++) {
                uint32_t aF[2][4], bF[4][4];
                #pragma unroll
                for (int mt = 0; mt < 2; mt++)
                    ldsm4(aF[mt], (aT + aLin + (uint32_t)mt * 2048u + (uint32_t)t * 32u) ^ xorv);
                #pragma unroll
                for (int ng = 0; ng < 4; ng++)
                    ldsm4(bF[ng], (bT + bLin + (uint32_t)ng * 2048u + (uint32_t)t * 32u) ^ xorv);
                #pragma unroll
                for (int mt = 0; mt < 2; mt++) {
                    #pragma unroll
                    for (int ng = 0; ng < 4; ng++) {
                        mma16816h(&acc[(mt * 8 + ng * 2) * 4],     aF[mt], bF[ng][0], bF[ng][2]);
                        mma16816h(&acc[(mt * 8 + ng * 2 + 1) * 4], aF[mt], bF[ng][1], bF[ng][3]);
                    }
                }
            }
        }
    }
    __syncthreads();

    // ---- epilogue: stage 64-oc quarters in smem, coalesced store ----
    float* sEp = (float*)(smem + DSM_EP);
    int r0l = lane >> 2, c0l = (lane & 3) * 2;
    for (int q = 0; q < 4; q++) {
        if (wn == q) {
            #pragma unroll
            for (int mt = 0; mt < 2; mt++) {
                int px = wm * 32 + mt * 16 + r0l;
                #pragma unroll
                for (int nn = 0; nn < 8; nn++) {
                    float* a4 = &acc[(mt * 8 + nn) * 4];
                    int ocl = nn * 8 + c0l;
                    sEp[ocl * 68 + px]           = a4[0];
                    sEp[(ocl + 1) * 68 + px]     = a4[1];
                    sEp[ocl * 68 + px + 8]       = a4[2];
                    sEp[(ocl + 1) * 68 + px + 8] = a4[3];
                }
            }
        }
        __syncthreads();
        for (int i = tid; i < 1024; i += 256) {
            int r = i >> 4, c = i & 15;
            float4 v = *(float4*)(sEp + r * 68 + c * 4);
            float bv = __ldg(bias + q * 64 + r);
            v.x += bv; v.y += bv; v.z += bv; v.w += bv;
            *(float4*)(out + ((size_t)b * OO + q * 64 + r) * SS + s0 + c * 4) = v;
        }
        __syncthreads();
    }
}

// ---------------- launch ----------------
extern "C" void kernel_launch(void* const* d_in, const int* in_sizes, int n_in,
                              void* d_out, int out_size) {
    const float* x    = (const float*)d_in[0];
    const float* ow   = (const float*)d_in[1];
    const float* ob   = (const float*)d_in[2];
    const float* mw   = (const float*)d_in[3];
    const float* mb   = (const float*)d_in[4];
    const float* w    = (const float*)d_in[5];
    const float* bias = (const float*)d_in[6];
    float* out = (float*)d_out;

    transpose_x_kernel<<<dim3(SS / 32, CC / 32, BB), dim3(32, 8)>>>(x);
    wprep_kernel<<<dim3(OO, NCH), 64>>>(w);
    owprep_kernel<<<dim3(32, NCH), 64>>>(ow, mw);

    cudaFuncSetAttribute(offmask_mma_kernel,
                         cudaFuncAttributeMaxDynamicSharedMemorySize, OSM_TOT);
    offmask_mma_kernel<<<BSS / 128, 256, OSM_TOT>>>(ob, mb);

    cudaFuncSetAttribute(deform_mma_kernel,
                         cudaFuncAttributeMaxDynamicSharedMemorySize, DSM_TOT);
    deform_mma_kernel<<<BSS / 64, 256, DSM_TOT>>>(out, bias);
}